// round 12
// baseline (speedup 1.0000x reference)
#include <cuda_runtime.h>
#include <cuda_fp16.h>
#include <math.h>

#define BPAR   4
#define NSEQ   4096
#define DMODEL 1024
#define NH     16
#define DH     64
#define WIN    256
#define MTOK   (BPAR * NSEQ)     /* 16384 */
#define QKVC   (3 * NH * DH)     /* 3072  */

// Scratch (allocation-free rule: __device__ globals)
__device__ __half g_xh[(size_t)MTOK * DMODEL];
__device__ __half g_xl[(size_t)MTOK * DMODEL];
__device__ __half g_qkvh[(size_t)MTOK * QKVC];
__device__ __half g_qkvl[(size_t)MTOK * QKVC];
__device__ __half g_ah[(size_t)MTOK * DMODEL];
__device__ __half g_wq[(size_t)QKVC * DMODEL];   // w_qkv^T fp16 [N][K]
__device__ __half g_wo[(size_t)DMODEL * DMODEL]; // w_out^T fp16 [N][K]

// ---------------------------------------------------------------------------
__device__ __forceinline__ unsigned smem_u32(const void* p) {
    unsigned a;
    asm("{ .reg .u64 t; cvta.to.shared.u64 t, %1; cvt.u32.u64 %0, t; }"
        : "=r"(a) : "l"(p));
    return a;
}
// split fp32 pair -> fp16x2 hi word + fp16x2 lo word (a = hi + lo to ~2^-23)
__device__ __forceinline__ void split2h(float x, float y, unsigned& h, unsigned& l) {
    __half2 hh = __floats2half2_rn(x, y);
    h = *reinterpret_cast<unsigned*>(&hh);
    float rx = x - __half2float(__low2half(hh));
    float ry = y - __half2float(__high2half(hh));
    __half2 ll = __floats2half2_rn(rx, ry);
    l = *reinterpret_cast<unsigned*>(&ll);
}
__device__ __forceinline__ unsigned pkh(float x, float y) {
    __half2 hh = __floats2half2_rn(x, y);
    return *reinterpret_cast<unsigned*>(&hh);
}
__device__ __forceinline__ void mma16816(
    float& c0, float& c1, float& c2, float& c3,
    unsigned a0, unsigned a1, unsigned a2, unsigned a3,
    unsigned b0, unsigned b1) {
    asm volatile(
        "mma.sync.aligned.m16n8k16.row.col.f32.f16.f16.f32 "
        "{%0,%1,%2,%3},{%4,%5,%6,%7},{%8,%9},{%0,%1,%2,%3};"
        : "+f"(c0), "+f"(c1), "+f"(c2), "+f"(c3)
        : "r"(a0), "r"(a1), "r"(a2), "r"(a3), "r"(b0), "r"(b1));
}
__device__ __forceinline__ void cp16(unsigned saddr, const void* g) {
    asm volatile("cp.async.cg.shared.global [%0], [%1], 16;"
                 :: "r"(saddr), "l"(g) : "memory");
}
#define LDSM4(r, a)                                                           \
    asm volatile("ldmatrix.sync.aligned.m8n8.x4.shared.b16 {%0,%1,%2,%3},[%4];" \
                 : "=r"((r)[0]), "=r"((r)[1]), "=r"((r)[2]), "=r"((r)[3])     \
                 : "r"(a))
#define LDSM4T(r, a)                                                          \
    asm volatile("ldmatrix.sync.aligned.m8n8.x4.trans.shared.b16 {%0,%1,%2,%3},[%4];" \
                 : "=r"((r)[0]), "=r"((r)[1]), "=r"((r)[2]), "=r"((r)[3])     \
                 : "r"(a))

// ---------------------------------------------------------------------------
// prepass: elementwise fp32 -> fp16 hi/lo
// ---------------------------------------------------------------------------
__global__ __launch_bounds__(256) void split_arr(
    const float4* __restrict__ src, uint4* __restrict__ hi,
    uint4* __restrict__ lo, int nvec8)
{
    int i = blockIdx.x * 256 + threadIdx.x;
    if (i >= nvec8) return;
    float4 f0 = src[2 * i], f1 = src[2 * i + 1];
    uint4 h, l;
    split2h(f0.x, f0.y, h.x, l.x); split2h(f0.z, f0.w, h.y, l.y);
    split2h(f1.x, f1.y, h.z, l.z); split2h(f1.z, f1.w, h.w, l.w);
    hi[i] = h; lo[i] = l;
}
// prepass: transpose + fp16 round, src [K][N] fp32 -> [N][K] fp16.
// columns n < nscale scaled by 0.125 (exact pow2; folds q-scale into W).
__global__ void tr_half(const float* __restrict__ src,
                        __half* __restrict__ dst, int K, int N, int nscale)
{
    __shared__ float tile[32][33];
    const int n0 = blockIdx.x * 32, k0 = blockIdx.y * 32;
    const int tx = threadIdx.x, ty = threadIdx.y;
    #pragma unroll
    for (int j = ty; j < 32; j += 8)
        tile[j][tx] = src[(size_t)(k0 + j) * N + n0 + tx];
    __syncthreads();
    #pragma unroll
    for (int j = ty; j < 32; j += 8) {
        float sc = (n0 + j < nscale) ? 0.125f : 1.0f;
        dst[(size_t)(n0 + j) * K + k0 + tx] = __float2half_rn(tile[tx][j] * sc);
    }
}

// ---------------------------------------------------------------------------
// fp16 HMMA GEMM, 2-stage cp.async pipeline, K chunk 64 (half the barriers).
// A hi/lo [M][K] fp16, B [N][K] fp16. CTAs with blockIdx.x < n2blk use 2
// terms, others 1 term. Lo-plane output stored only for n0 < nlo.
// 128x128 CTA tile, 256 thr (2x4 warps -> 64x32 warp tile).
// smem rows: 64 fp16 = 128B data + 16B pad = 144B (36 words; 4g+w banks, CF).
// ---------------------------------------------------------------------------
#define TILE_B 18432
#define STG_B  55296
#define GSMEM  (2 * STG_B)

__device__ __forceinline__ void gload(
    unsigned sb, int st, int tid, bool two,
    const __half* b0, const __half* b1, const __half* b2, int K, int k0)
{
    const __half* base[3] = {b0, b1, b2};
    const int row = tid >> 1;           // 0..127
    const int sg  = (tid & 1) * 4;      // 4 x 16B segments per half-row
    #pragma unroll
    for (int tl = 0; tl < 3; tl++) {
        if (tl == 1 && !two) continue;  // skip Al tile for 1-term CTAs
        const __half* gp = base[tl] + (size_t)row * K + k0 + sg * 8;
        unsigned sp = sb + st * STG_B + tl * TILE_B + row * 144 + sg * 16;
        #pragma unroll
        for (int i = 0; i < 4; i++) cp16(sp + i * 16, gp + i * 8);
    }
    asm volatile("cp.async.commit_group;" ::: "memory");
}

__global__ __launch_bounds__(256, 2) void gemm_mma(
    const __half* __restrict__ Ah, const __half* __restrict__ Al,
    const __half* __restrict__ B,
    float* __restrict__ Cf, __half* __restrict__ Ch,
    __half* __restrict__ Cl, int M, int N, int K, int n2blk, int nlo)
{
    extern __shared__ char dsm[];
    const unsigned sb = smem_u32(dsm);

    const int tid = threadIdx.x;
    const int wid = tid >> 5, lid = tid & 31;
    const int g = lid >> 2, t = lid & 3;
    const int wm = (wid >> 2) * 64;
    const int wn = (wid & 3) * 32;
    const int m0 = blockIdx.y * 128, n0 = blockIdx.x * 128;
    const bool two = (int)blockIdx.x < n2blk;

    const __half* a_h = Ah + (size_t)m0 * K;
    const __half* a_l = Al + (size_t)m0 * K;
    const __half* b_p = B + (size_t)n0 * K;

    float acc[4][4][4];
    #pragma unroll
    for (int i = 0; i < 4; i++)
        #pragma unroll
        for (int j = 0; j < 4; j++)
            #pragma unroll
            for (int e = 0; e < 4; e++) acc[i][j][e] = 0.f;

    const int nk = K >> 6;
    gload(sb, 0, tid, two, a_h, a_l, b_p, K, 0);

    for (int kc = 0; kc < nk; kc++) {
        if (kc + 1 < nk) {
            gload(sb, (kc + 1) & 1, tid, two, a_h, a_l, b_p, K, (kc + 1) << 6);
            asm volatile("cp.async.wait_group 1;" ::: "memory");
        } else {
            asm volatile("cp.async.wait_group 0;" ::: "memory");
        }
        __syncthreads();

        const int st = kc & 1;
        const unsigned* pAh = reinterpret_cast<const unsigned*>(dsm + st * STG_B);
        const unsigned* pAl = pAh + 4608;
        const unsigned* pB  = pAh + 9216;

        #pragma unroll
        for (int s = 0; s < 4; s++) {
            const int w = s * 8 + t;
            unsigned ah[4][4], al[4][4];
            #pragma unroll
            for (int tm = 0; tm < 4; tm++) {
                const int r0 = (wm + tm * 16 + g) * 36;
                const int r1 = r0 + 8 * 36;
                ah[tm][0] = pAh[r0 + w];     ah[tm][1] = pAh[r1 + w];
                ah[tm][2] = pAh[r0 + w + 4]; ah[tm][3] = pAh[r1 + w + 4];
                if (two) {
                    al[tm][0] = pAl[r0 + w];     al[tm][1] = pAl[r1 + w];
                    al[tm][2] = pAl[r0 + w + 4]; al[tm][3] = pAl[r1 + w + 4];
                }
            }
            #pragma unroll
            for (int tn = 0; tn < 4; tn++) {
                const int nr = (wn + tn * 8 + g) * 36;
                const unsigned b0 = pB[nr + w], b1 = pB[nr + w + 4];
                #pragma unroll
                for (int tm = 0; tm < 4; tm++) {
                    float* c = acc[tm][tn];
                    mma16816(c[0], c[1], c[2], c[3],
                             ah[tm][0], ah[tm][1], ah[tm][2], ah[tm][3], b0, b1);
                    if (two)
                        mma16816(c[0], c[1], c[2], c[3],
                                 al[tm][0], al[tm][1], al[tm][2], al[tm][3], b0, b1);
                }
            }
        }
        __syncthreads();
    }

    const bool wlo = (Cl != nullptr) && (n0 < nlo);
    #pragma unroll
    for (int tm = 0; tm < 4; tm++) {
        #pragma unroll
        for (int tn = 0; tn < 4; tn++) {
            float* c = acc[tm][tn];
            size_t r0 = (size_t)(m0 + wm + tm * 16 + g) * N + n0 + wn + tn * 8 + 2 * t;
            if (Cf) {
                *reinterpret_cast<float2*>(Cf + r0)                 = make_float2(c[0], c[1]);
                *reinterpret_cast<float2*>(Cf + r0 + 8 * (size_t)N) = make_float2(c[2], c[3]);
            } else {
                unsigned hw, lw;
                split2h(c[0], c[1], hw, lw);
                *reinterpret_cast<unsigned*>(Ch + r0) = hw;
                if (wlo) *reinterpret_cast<unsigned*>(Cl + r0) = lw;
                split2h(c[2], c[3], hw, lw);
                *reinterpret_cast<unsigned*>(Ch + r0 + 8 * (size_t)N) = hw;
                if (wlo) *reinterpret_cast<unsigned*>(Cl + r0 + 8 * (size_t)N) = lw;
            }
        }
    }
}

// ---------------------------------------------------------------------------
// fp16 HMMA sliding-window attention. grid = (32, 64), 256 thr, occupancy 2.
// Q 2-plane (hi/lo), K/V hi plane only. Scores processed in 8-tile halves.
// Output: single fp16 hi plane.
// ---------------------------------------------------------------------------
#define RB    144
#define QPL   18432
#define ASMEM (6 * QPL)

__global__ __launch_bounds__(256, 2) void swa_mma(
    const __half* __restrict__ qkvh, const __half* __restrict__ qkvl,
    __half* __restrict__ oh)
{
    extern __shared__ char sm[];
    const unsigned sb = smem_u32(sm);
    const int blkq = blockIdx.x;
    const int bh = blockIdx.y, b = bh >> 4, hh = bh & 15;
    const int tid = threadIdx.x, w = tid >> 5, lid = tid & 31;
    const int g = lid >> 2, t = lid & 3;
    const int q0 = blkq * 128;
    const size_t tokb = (size_t)b * NSEQ;

    const unsigned sQ = sb;
    const unsigned sK = sb + 2 * QPL;
    const unsigned sV = sb + 4 * QPL;

    {
        int r = tid >> 1, hl = tid & 1;
        const __half* src = (hl ? qkvl : qkvh) + (tokb + q0 + r) * QKVC + hh * DH;
        unsigned dst = sQ + hl * QPL + r * RB;
        #pragma unroll
        for (int s = 0; s < 8; s++) cp16(dst + s * 16, src + s * 8);
    }
    asm volatile("cp.async.commit_group;" ::: "memory");

    const int cstart = (q0 >= 256) ? 0 : (q0 >= 128 ? 1 : 2);

    auto ldkv = [&](int c, int st) {
        const int kb = q0 - 256 + c * 128;
        const int r = tid & 127;
        const int isv = tid >> 7;
        const size_t row = tokb + kb + r;
        const int off = (isv ? 2 * DMODEL : DMODEL) + hh * DH;
        const __half* sh = qkvh + row * QKVC + off;
        unsigned base = (isv ? sV : sK) + st * QPL + r * RB;
        #pragma unroll
        for (int s = 0; s < 8; s++) cp16(base + s * 16, sh + s * 8);
        asm volatile("cp.async.commit_group;" ::: "memory");
    };

    ldkv(cstart, 0);
    asm volatile("cp.async.wait_group 0;" ::: "memory");
    __syncthreads();

    unsigned qh[4][4], ql[4][4];
    {
        unsigned ab = sQ + (w * 16 + (lid & 15)) * RB + (lid >> 4) * 16;
        #pragma unroll
        for (int ks = 0; ks < 4; ks++) {
            LDSM4(qh[ks], ab + ks * 32);
            LDSM4(ql[ks], ab + QPL + ks * 32);
        }
    }

    float O[8][4];
    #pragma unroll
    for (int i = 0; i < 8; i++)
        #pragma unroll
        for (int e = 0; e < 4; e++) O[i][e] = 0.f;
    float m0 = -1e30f, m1 = -1e30f, l0 = 0.f, l1 = 0.f;
    const int qi0 = q0 + w * 16 + g, qi1 = qi0 + 8;

    const unsigned klane = (lid & 7) * RB + (lid >> 3) * 16;
    const unsigned vlane = (lid & 15) * RB + (lid >> 4) * 16;

    for (int c = cstart; c <= 2; ++c) {
        const int st = (c - cstart) & 1;
        if (c < 2) ldkv(c + 1, st ^ 1);

        const int kb = q0 - 256 + c * 128;
        const int tnlo = (c == 0) ? 2 * w : 0;
        const int tnhi = (c == 2) ? 2 * w + 1 : 15;
        const int jlo = (c == 0) ? w : 0;
        const int jhi = (c == 2) ? w : 7;
        const unsigned kbase = sK + st * QPL + klane;
        const unsigned vbase = sV + st * QPL + vlane;

        #pragma unroll
        for (int hf = 0; hf < 2; hf++) {
            const int lo  = (tnlo > hf * 8) ? tnlo : hf * 8;
            const int hi2 = (tnhi < hf * 8 + 7) ? tnhi : hf * 8 + 7;
            if (lo > hi2) continue;

            float S[8][4];
            #pragma unroll
            for (int i = 0; i < 8; i++) {
                const int tt = hf * 8 + i;
                if (tt < lo || tt > hi2) continue;
                S[i][0] = S[i][1] = S[i][2] = S[i][3] = 0.f;
                #pragma unroll
                for (int sp = 0; sp < 2; sp++) {
                    unsigned kh[4];
                    LDSM4(kh, kbase + tt * (8 * RB) + sp * 64);
                    float* c4 = S[i];
                    mma16816(c4[0], c4[1], c4[2], c4[3],
                             qh[2*sp][0], qh[2*sp][1], qh[2*sp][2], qh[2*sp][3], kh[0], kh[1]);
                    mma16816(c4[0], c4[1], c4[2], c4[3],
                             ql[2*sp][0], ql[2*sp][1], ql[2*sp][2], ql[2*sp][3], kh[0], kh[1]);
                    mma16816(c4[0], c4[1], c4[2], c4[3],
                             qh[2*sp+1][0], qh[2*sp+1][1], qh[2*sp+1][2], qh[2*sp+1][3], kh[2], kh[3]);
                    mma16816(c4[0], c4[1], c4[2], c4[3],
                             ql[2*sp+1][0], ql[2*sp+1][1], ql[2*sp+1][2], ql[2*sp+1][3], kh[2], kh[3]);
                }
            }

            float cm0 = -1e30f, cm1 = -1e30f;
            #pragma unroll
            for (int i = 0; i < 8; i++) {
                const int tt = hf * 8 + i;
                if (tt < lo || tt > hi2) continue;
                const int k0c = kb + tt * 8 + 2 * t;
                if (c == 0) {
                    if (k0c     < qi0 - 255) S[i][0] = -1e30f;
                    if (k0c + 1 < qi0 - 255) S[i][1] = -1e30f;
                    if (k0c     < qi1 - 255) S[i][2] = -1e30f;
                    if (k0c + 1 < qi1 - 255) S[i][3] = -1e30f;
                } else if (c == 2) {
                    if (k0c     > qi0) S[i][0] = -1e30f;
                    if (k0c + 1 > qi0) S[i][1] = -1e30f;
                    if (k0c     > qi1) S[i][2] = -1e30f;
                    if (k0c + 1 > qi1) S[i][3] = -1e30f;
                }
                cm0 = fmaxf(cm0, fmaxf(S[i][0], S[i][1]));
                cm1 = fmaxf(cm1, fmaxf(S[i][2], S[i][3]));
            }
            cm0 = fmaxf(cm0, __shfl_xor_sync(0xFFFFFFFFu, cm0, 1));
            cm0 = fmaxf(cm0, __shfl_xor_sync(0xFFFFFFFFu, cm0, 2));
            cm1 = fmaxf(cm1, __shfl_xor_sync(0xFFFFFFFFu, cm1, 1));
            cm1 = fmaxf(cm1, __shfl_xor_sync(0xFFFFFFFFu, cm1, 2));
            const float mn0 = fmaxf(m0, cm0), mn1 = fmaxf(m1, cm1);
            const float corr0 = __expf(m0 - mn0), corr1 = __expf(m1 - mn1);
            m0 = mn0; m1 = mn1;

            float ls0 = 0.f, ls1 = 0.f;
            #pragma unroll
            for (int i = 0; i < 8; i++) {
                const int tt = hf * 8 + i;
                if (tt < lo || tt > hi2) continue;
                S[i][0] = __expf(S[i][0] - m0);
                S[i][1] = __expf(S[i][1] - m0);
                S[i][2] = __expf(S[i][2] - m1);
                S[i][3] = __expf(S[i][3] - m1);
                ls0 += S[i][0] + S[i][1];
                ls1 += S[i][2] + S[i][3];
            }
            l0 = l0 * corr0 + ls0;
            l1 = l1 * corr1 + ls1;
            #pragma unroll
            for (int i = 0; i < 8; i++) {
                O[i][0] *= corr0; O[i][1] *= corr0;
                O[i][2] *= corr1; O[i][3] *= corr1;
            }

            #pragma unroll
            for (int j = 0; j < 4; j++) {
                const int jj2 = hf * 4 + j;
                if (jj2 < jlo || jj2 > jhi) continue;
                unsigned ph[4];
                ph[0] = pkh(S[2*j][0],   S[2*j][1]);
                ph[1] = pkh(S[2*j][2],   S[2*j][3]);
                ph[2] = pkh(S[2*j+1][0], S[2*j+1][1]);
                ph[3] = pkh(S[2*j+1][2], S[2*j+1][3]);
                #pragma unroll
                for (int tp = 0; tp < 4; tp++) {
                    unsigned vh[4];
                    LDSM4T(vh, vbase + jj2 * (16 * RB) + tp * 32);
                    float* cA = O[2 * tp];
                    float* cB = O[2 * tp + 1];
                    mma16816(cA[0], cA[1], cA[2], cA[3],
                             ph[0], ph[1], ph[2], ph[3], vh[0], vh[1]);
                    mma16816(cB[0], cB[1], cB[2], cB[3],
                             ph[0], ph[1], ph[2], ph[3], vh[2], vh[3]);
                }
            }
        }

        if (c < 2) asm volatile("cp.async.wait_group 0;" ::: "memory");
        __syncthreads();
    }

    l0 += __shfl_xor_sync(0xFFFFFFFFu, l0, 1);
    l0 += __shfl_xor_sync(0xFFFFFFFFu, l0, 2);
    l1 += __shfl_xor_sync(0xFFFFFFFFu, l1, 1);
    l1 += __shfl_xor_sync(0xFFFFFFFFu, l1, 2);
    const float i0 = 1.f / l0, i1 = 1.f / l1;
    const size_t t0 = (tokb + q0 + w * 16 + g) * DMODEL + hh * DH;
    const size_t t1 = t0 + 8 * DMODEL;
    #pragma unroll
    for (int tp = 0; tp < 8; tp++) {
        const int col = tp * 8 + 2 * t;
        *reinterpret_cast<unsigned*>(oh + t0 + col) = pkh(O[tp][0] * i0, O[tp][1] * i0);
        *reinterpret_cast<unsigned*>(oh + t1 + col) = pkh(O[tp][2] * i1, O[tp][3] * i1);
    }
}

// ---------------------------------------------------------------------------
extern "C" void kernel_launch(void* const* d_in, const int* in_sizes, int n_in,
                              void* d_out, int out_size)
{
    const float* x     = (const float*)d_in[0];
    const float* w_qkv = (const float*)d_in[1];
    const float* w_out = (const float*)d_in[2];
    float*       out   = (float*)d_out;

    __half *xh, *xl, *qkvh, *qkvl, *ah, *wq, *wo;
    cudaGetSymbolAddress((void**)&xh, g_xh);
    cudaGetSymbolAddress((void**)&xl, g_xl);
    cudaGetSymbolAddress((void**)&qkvh, g_qkvh);
    cudaGetSymbolAddress((void**)&qkvl, g_qkvl);
    cudaGetSymbolAddress((void**)&ah, g_ah);
    cudaGetSymbolAddress((void**)&wq, g_wq);
    cudaGetSymbolAddress((void**)&wo, g_wo);

    cudaFuncSetAttribute(gemm_mma, cudaFuncAttributeMaxDynamicSharedMemorySize, GSMEM);
    cudaFuncSetAttribute(swa_mma, cudaFuncAttributeMaxDynamicSharedMemorySize, ASMEM);

    const int nv8 = MTOK * DMODEL / 8;
    split_arr<<<(nv8 + 255) / 256, 256>>>((const float4*)x, (uint4*)xh, (uint4*)xl, nv8);
    tr_half<<<dim3(QKVC / 32, DMODEL / 32), dim3(32, 8)>>>(w_qkv, wq, DMODEL, QKVC, DMODEL);
    tr_half<<<dim3(DMODEL / 32, DMODEL / 32), dim3(32, 8)>>>(w_out, wo, DMODEL, DMODEL, 0);

    // QKV: q columns (blockIdx.x < 8) 2-term; k,v 1-term; lo stored for q only.
    gemm_mma<<<dim3(QKVC / 128, MTOK / 128), 256, GSMEM>>>(
        xh, xl, wq, nullptr, qkvh, qkvl, MTOK, QKVC, DMODEL, 8, 1024);
    swa_mma<<<dim3(NSEQ / 128, BPAR * NH), 256, ASMEM>>>(qkvh, qkvl, ah);
    // OUT: fully 1-term.
    gemm_mma<<<dim3(DMODEL / 128, MTOK / 128), 256, GSMEM>>>(
        ah, ah, wo, out, nullptr, nullptr, MTOK, DMODEL, DMODEL, 0, 0);
}

// round 13
// speedup vs baseline: 1.5859x; 1.5859x over previous
#include <cuda_runtime.h>
#include <cuda_fp16.h>
#include <math.h>

#define BPAR   4
#define NSEQ   4096
#define DMODEL 1024
#define NH     16
#define DH     64
#define WIN    256
#define MTOK   (BPAR * NSEQ)     /* 16384 */
#define QKVC   (3 * NH * DH)     /* 3072  */

// Scratch (allocation-free rule: __device__ globals)
__device__ __half g_xh[(size_t)MTOK * DMODEL];
__device__ __half g_qkvh[(size_t)MTOK * QKVC];
__device__ __half g_ah[(size_t)MTOK * DMODEL];
__device__ __half g_wq[(size_t)QKVC * DMODEL];   // w_qkv^T fp16 [N][K]
__device__ __half g_wo[(size_t)DMODEL * DMODEL]; // w_out^T fp16 [N][K]

// ---------------------------------------------------------------------------
__device__ __forceinline__ unsigned smem_u32(const void* p) {
    unsigned a;
    asm("{ .reg .u64 t; cvta.to.shared.u64 t, %1; cvt.u32.u64 %0, t; }"
        : "=r"(a) : "l"(p));
    return a;
}
__device__ __forceinline__ unsigned pkh(float x, float y) {
    __half2 hh = __floats2half2_rn(x, y);
    return *reinterpret_cast<unsigned*>(&hh);
}
__device__ __forceinline__ void mma16816(
    float& c0, float& c1, float& c2, float& c3,
    unsigned a0, unsigned a1, unsigned a2, unsigned a3,
    unsigned b0, unsigned b1) {
    asm volatile(
        "mma.sync.aligned.m16n8k16.row.col.f32.f16.f16.f32 "
        "{%0,%1,%2,%3},{%4,%5,%6,%7},{%8,%9},{%0,%1,%2,%3};"
        : "+f"(c0), "+f"(c1), "+f"(c2), "+f"(c3)
        : "r"(a0), "r"(a1), "r"(a2), "r"(a3), "r"(b0), "r"(b1));
}
__device__ __forceinline__ void cp16(unsigned saddr, const void* g) {
    asm volatile("cp.async.cg.shared.global [%0], [%1], 16;"
                 :: "r"(saddr), "l"(g) : "memory");
}
#define LDSM4(r, a)                                                           \
    asm volatile("ldmatrix.sync.aligned.m8n8.x4.shared.b16 {%0,%1,%2,%3},[%4];" \
                 : "=r"((r)[0]), "=r"((r)[1]), "=r"((r)[2]), "=r"((r)[3])     \
                 : "r"(a))
#define LDSM4T(r, a)                                                          \
    asm volatile("ldmatrix.sync.aligned.m8n8.x4.trans.shared.b16 {%0,%1,%2,%3},[%4];" \
                 : "=r"((r)[0]), "=r"((r)[1]), "=r"((r)[2]), "=r"((r)[3])     \
                 : "r"(a))

// ---------------------------------------------------------------------------
// prepass: elementwise fp32 -> fp16 (single plane)
// ---------------------------------------------------------------------------
__global__ __launch_bounds__(256) void conv_half(
    const float4* __restrict__ src, uint4* __restrict__ dst, int nvec8)
{
    int i = blockIdx.x * 256 + threadIdx.x;
    if (i >= nvec8) return;
    float4 f0 = src[2 * i], f1 = src[2 * i + 1];
    uint4 h;
    h.x = pkh(f0.x, f0.y); h.y = pkh(f0.z, f0.w);
    h.z = pkh(f1.x, f1.y); h.w = pkh(f1.z, f1.w);
    dst[i] = h;
}
// prepass: transpose + fp16 round, src [K][N] fp32 -> [N][K] fp16.
// columns n < nscale scaled by 0.125 (exact pow2; folds q-scale into W).
__global__ void tr_half(const float* __restrict__ src,
                        __half* __restrict__ dst, int K, int N, int nscale)
{
    __shared__ float tile[32][33];
    const int n0 = blockIdx.x * 32, k0 = blockIdx.y * 32;
    const int tx = threadIdx.x, ty = threadIdx.y;
    #pragma unroll
    for (int j = ty; j < 32; j += 8)
        tile[j][tx] = src[(size_t)(k0 + j) * N + n0 + tx];
    __syncthreads();
    #pragma unroll
    for (int j = ty; j < 32; j += 8) {
        float sc = (n0 + j < nscale) ? 0.125f : 1.0f;
        dst[(size_t)(n0 + j) * K + k0 + tx] = __float2half_rn(tile[tx][j] * sc);
    }
}

// ---------------------------------------------------------------------------
// 1-term fp16 HMMA GEMM (R10-proven skeleton), 2-stage cp.async, K chunk 32.
// A [M][K] fp16, B [N][K] fp16. Out: fp32 Cf OR fp16 Ch.
// 128x128 CTA tile, 256 thr (2x4 warps -> 64x32 warp tile).
// ---------------------------------------------------------------------------
#define TILE_B 10240
#define STG_B  20480
#define GSMEM  (2 * STG_B)

__device__ __forceinline__ void gload(
    unsigned sb, int st, int tid,
    const __half* a, const __half* b, int K, int k0)
{
    const __half* base[2] = {a, b};
    const int rlo = tid >> 2;
    const int pel = (tid & 3) << 3;
    const int pby = (tid & 3) << 4;
    #pragma unroll
    for (int i = 0; i < 4; i++) {
        const int tl  = i >> 1;
        const int row = ((i & 1) << 6) + rlo;
        cp16(sb + st * STG_B + tl * TILE_B + row * 80 + pby,
             base[tl] + (size_t)row * K + k0 + pel);
    }
    asm volatile("cp.async.commit_group;" ::: "memory");
}

__global__ __launch_bounds__(256, 2) void gemm_mma(
    const __half* __restrict__ A, const __half* __restrict__ B,
    float* __restrict__ Cf, __half* __restrict__ Ch, int M, int N, int K)
{
    extern __shared__ char dsm[];
    const unsigned sb = smem_u32(dsm);

    const int tid = threadIdx.x;
    const int wid = tid >> 5, lid = tid & 31;
    const int g = lid >> 2, t = lid & 3;
    const int wm = (wid >> 2) * 64;
    const int wn = (wid & 3) * 32;
    const int m0 = blockIdx.y * 128, n0 = blockIdx.x * 128;

    const __half* a_p = A + (size_t)m0 * K;
    const __half* b_p = B + (size_t)n0 * K;

    float acc[4][4][4];
    #pragma unroll
    for (int i = 0; i < 4; i++)
        #pragma unroll
        for (int j = 0; j < 4; j++)
            #pragma unroll
            for (int e = 0; e < 4; e++) acc[i][j][e] = 0.f;

    const int nk = K >> 5;
    gload(sb, 0, tid, a_p, b_p, K, 0);

    for (int kc = 0; kc < nk; kc++) {
        if (kc + 1 < nk) {
            gload(sb, (kc + 1) & 1, tid, a_p, b_p, K, (kc + 1) << 5);
            asm volatile("cp.async.wait_group 1;" ::: "memory");
        } else {
            asm volatile("cp.async.wait_group 0;" ::: "memory");
        }
        __syncthreads();

        const int st = kc & 1;
        const unsigned* pA = reinterpret_cast<const unsigned*>(dsm + st * STG_B);
        const unsigned* pB = pA + 2560;

        #pragma unroll
        for (int s = 0; s < 2; s++) {
            const int w = s * 8 + t;
            unsigned a[4][4];
            #pragma unroll
            for (int tm = 0; tm < 4; tm++) {
                const int r0 = (wm + tm * 16 + g) * 20;
                const int r1 = r0 + 8 * 20;
                a[tm][0] = pA[r0 + w];     a[tm][1] = pA[r1 + w];
                a[tm][2] = pA[r0 + w + 4]; a[tm][3] = pA[r1 + w + 4];
            }
            #pragma unroll
            for (int tn = 0; tn < 4; tn++) {
                const int nr = (wn + tn * 8 + g) * 20;
                const unsigned b0 = pB[nr + w], b1 = pB[nr + w + 4];
                #pragma unroll
                for (int tm = 0; tm < 4; tm++) {
                    float* c = acc[tm][tn];
                    mma16816(c[0], c[1], c[2], c[3],
                             a[tm][0], a[tm][1], a[tm][2], a[tm][3], b0, b1);
                }
            }
        }
        __syncthreads();
    }

    #pragma unroll
    for (int tm = 0; tm < 4; tm++) {
        #pragma unroll
        for (int tn = 0; tn < 4; tn++) {
            float* c = acc[tm][tn];
            size_t r0 = (size_t)(m0 + wm + tm * 16 + g) * N + n0 + wn + tn * 8 + 2 * t;
            if (Cf) {
                *reinterpret_cast<float2*>(Cf + r0)                 = make_float2(c[0], c[1]);
                *reinterpret_cast<float2*>(Cf + r0 + 8 * (size_t)N) = make_float2(c[2], c[3]);
            } else {
                *reinterpret_cast<unsigned*>(Ch + r0) = pkh(c[0], c[1]);
                *reinterpret_cast<unsigned*>(Ch + r0 + 8 * (size_t)N) = pkh(c[2], c[3]);
            }
        }
    }
}

// ---------------------------------------------------------------------------
// fp16 HMMA sliding-window attention. grid = (32, 64), 256 thr, occupancy 2.
// Q/K/V single fp16 plane. Scores 2 MMAs per tile; 8-tile halves for regs.
// Output: single fp16 plane.
// ---------------------------------------------------------------------------
#define RB    144
#define QPL   18432              /* one 128-row plane */
#define ASMEM (5 * QPL)          /* Q + K x2 stages + V x2 = 92160 */

__global__ __launch_bounds__(256, 2) void swa_mma(
    const __half* __restrict__ qkvh, __half* __restrict__ oh)
{
    extern __shared__ char sm[];
    const unsigned sb = smem_u32(sm);
    const int blkq = blockIdx.x;
    const int bh = blockIdx.y, b = bh >> 4, hh = bh & 15;
    const int tid = threadIdx.x, w = tid >> 5, lid = tid & 31;
    const int g = lid >> 2, t = lid & 3;
    const int q0 = blkq * 128;
    const size_t tokb = (size_t)b * NSEQ;

    const unsigned sQ = sb;
    const unsigned sK = sb + QPL;          // [stage]
    const unsigned sV = sb + 3 * QPL;      // [stage]

    // stage Q (single plane): 2 threads per row, 64B each
    {
        int r = tid >> 1;
        const __half* src = qkvh + (tokb + q0 + r) * QKVC + hh * DH + (tid & 1) * 32;
        unsigned dst = sQ + r * RB + (tid & 1) * 64;
        #pragma unroll
        for (int s = 0; s < 4; s++) cp16(dst + s * 16, src + s * 8);
    }
    asm volatile("cp.async.commit_group;" ::: "memory");

    const int cstart = (q0 >= 256) ? 0 : (q0 >= 128 ? 1 : 2);

    auto ldkv = [&](int c, int st) {
        const int kb = q0 - 256 + c * 128;
        const int r = tid & 127;
        const int isv = tid >> 7;
        const size_t row = tokb + kb + r;
        const int off = (isv ? 2 * DMODEL : DMODEL) + hh * DH;
        const __half* sh = qkvh + row * QKVC + off;
        unsigned base = (isv ? sV : sK) + st * QPL + r * RB;
        #pragma unroll
        for (int s = 0; s < 8; s++) cp16(base + s * 16, sh + s * 8);
        asm volatile("cp.async.commit_group;" ::: "memory");
    };

    ldkv(cstart, 0);
    asm volatile("cp.async.wait_group 0;" ::: "memory");
    __syncthreads();

    unsigned qh[4][4];
    {
        unsigned ab = sQ + (w * 16 + (lid & 15)) * RB + (lid >> 4) * 16;
        #pragma unroll
        for (int ks = 0; ks < 4; ks++) LDSM4(qh[ks], ab + ks * 32);
    }

    float O[8][4];
    #pragma unroll
    for (int i = 0; i < 8; i++)
        #pragma unroll
        for (int e = 0; e < 4; e++) O[i][e] = 0.f;
    float m0 = -1e30f, m1 = -1e30f, l0 = 0.f, l1 = 0.f;
    const int qi0 = q0 + w * 16 + g, qi1 = qi0 + 8;

    const unsigned klane = (lid & 7) * RB + (lid >> 3) * 16;
    const unsigned vlane = (lid & 15) * RB + (lid >> 4) * 16;

    for (int c = cstart; c <= 2; ++c) {
        const int st = (c - cstart) & 1;
        if (c < 2) ldkv(c + 1, st ^ 1);

        const int kb = q0 - 256 + c * 128;
        const int tnlo = (c == 0) ? 2 * w : 0;
        const int tnhi = (c == 2) ? 2 * w + 1 : 15;
        const int jlo = (c == 0) ? w : 0;
        const int jhi = (c == 2) ? w : 7;
        const unsigned kbase = sK + st * QPL + klane;
        const unsigned vbase = sV + st * QPL + vlane;

        #pragma unroll
        for (int hf = 0; hf < 2; hf++) {
            const int lo  = (tnlo > hf * 8) ? tnlo : hf * 8;
            const int hi2 = (tnhi < hf * 8 + 7) ? tnhi : hf * 8 + 7;
            if (lo > hi2) continue;

            float S[8][4];
            #pragma unroll
            for (int i = 0; i < 8; i++) {
                const int tt = hf * 8 + i;
                if (tt < lo || tt > hi2) continue;
                S[i][0] = S[i][1] = S[i][2] = S[i][3] = 0.f;
                #pragma unroll
                for (int sp = 0; sp < 2; sp++) {
                    unsigned kh[4];
                    LDSM4(kh, kbase + tt * (8 * RB) + sp * 64);
                    float* c4 = S[i];
                    mma16816(c4[0], c4[1], c4[2], c4[3],
                             qh[2*sp][0], qh[2*sp][1], qh[2*sp][2], qh[2*sp][3], kh[0], kh[1]);
                    mma16816(c4[0], c4[1], c4[2], c4[3],
                             qh[2*sp+1][0], qh[2*sp+1][1], qh[2*sp+1][2], qh[2*sp+1][3], kh[2], kh[3]);
                }
            }

            float cm0 = -1e30f, cm1 = -1e30f;
            #pragma unroll
            for (int i = 0; i < 8; i++) {
                const int tt = hf * 8 + i;
                if (tt < lo || tt > hi2) continue;
                const int k0c = kb + tt * 8 + 2 * t;
                if (c == 0) {
                    if (k0c     < qi0 - 255) S[i][0] = -1e30f;
                    if (k0c + 1 < qi0 - 255) S[i][1] = -1e30f;
                    if (k0c     < qi1 - 255) S[i][2] = -1e30f;
                    if (k0c + 1 < qi1 - 255) S[i][3] = -1e30f;
                } else if (c == 2) {
                    if (k0c     > qi0) S[i][0] = -1e30f;
                    if (k0c + 1 > qi0) S[i][1] = -1e30f;
                    if (k0c     > qi1) S[i][2] = -1e30f;
                    if (k0c + 1 > qi1) S[i][3] = -1e30f;
                }
                cm0 = fmaxf(cm0, fmaxf(S[i][0], S[i][1]));
                cm1 = fmaxf(cm1, fmaxf(S[i][2], S[i][3]));
            }
            cm0 = fmaxf(cm0, __shfl_xor_sync(0xFFFFFFFFu, cm0, 1));
            cm0 = fmaxf(cm0, __shfl_xor_sync(0xFFFFFFFFu, cm0, 2));
            cm1 = fmaxf(cm1, __shfl_xor_sync(0xFFFFFFFFu, cm1, 1));
            cm1 = fmaxf(cm1, __shfl_xor_sync(0xFFFFFFFFu, cm1, 2));
            const float mn0 = fmaxf(m0, cm0), mn1 = fmaxf(m1, cm1);
            const float corr0 = __expf(m0 - mn0), corr1 = __expf(m1 - mn1);
            m0 = mn0; m1 = mn1;

            float ls0 = 0.f, ls1 = 0.f;
            #pragma unroll
            for (int i = 0; i < 8; i++) {
                const int tt = hf * 8 + i;
                if (tt < lo || tt > hi2) continue;
                S[i][0] = __expf(S[i][0] - m0);
                S[i][1] = __expf(S[i][1] - m0);
                S[i][2] = __expf(S[i][2] - m1);
                S[i][3] = __expf(S[i][3] - m1);
                ls0 += S[i][0] + S[i][1];
                ls1 += S[i][2] + S[i][3];
            }
            l0 = l0 * corr0 + ls0;
            l1 = l1 * corr1 + ls1;
            #pragma unroll
            for (int i = 0; i < 8; i++) {
                O[i][0] *= corr0; O[i][1] *= corr0;
                O[i][2] *= corr1; O[i][3] *= corr1;
            }

            #pragma unroll
            for (int j = 0; j < 4; j++) {
                const int jj2 = hf * 4 + j;
                if (jj2 < jlo || jj2 > jhi) continue;
                unsigned ph[4];
                ph[0] = pkh(S[2*j][0],   S[2*j][1]);
                ph[1] = pkh(S[2*j][2],   S[2*j][3]);
                ph[2] = pkh(S[2*j+1][0], S[2*j+1][1]);
                ph[3] = pkh(S[2*j+1][2], S[2*j+1][3]);
                #pragma unroll
                for (int tp = 0; tp < 4; tp++) {
                    unsigned vh[4];
                    LDSM4T(vh, vbase + jj2 * (16 * RB) + tp * 32);
                    float* cA = O[2 * tp];
                    float* cB = O[2 * tp + 1];
                    mma16816(cA[0], cA[1], cA[2], cA[3],
                             ph[0], ph[1], ph[2], ph[3], vh[0], vh[1]);
                    mma16816(cB[0], cB[1], cB[2], cB[3],
                             ph[0], ph[1], ph[2], ph[3], vh[2], vh[3]);
                }
            }
        }

        if (c < 2) asm volatile("cp.async.wait_group 0;" ::: "memory");
        __syncthreads();
    }

    l0 += __shfl_xor_sync(0xFFFFFFFFu, l0, 1);
    l0 += __shfl_xor_sync(0xFFFFFFFFu, l0, 2);
    l1 += __shfl_xor_sync(0xFFFFFFFFu, l1, 1);
    l1 += __shfl_xor_sync(0xFFFFFFFFu, l1, 2);
    const float i0 = 1.f / l0, i1 = 1.f / l1;
    const size_t t0 = (tokb + q0 + w * 16 + g) * DMODEL + hh * DH;
    const size_t t1 = t0 + 8 * DMODEL;
    #pragma unroll
    for (int tp = 0; tp < 8; tp++) {
        const int col = tp * 8 + 2 * t;
        *reinterpret_cast<unsigned*>(oh + t0 + col) = pkh(O[tp][0] * i0, O[tp][1] * i0);
        *reinterpret_cast<unsigned*>(oh + t1 + col) = pkh(O[tp][2] * i1, O[tp][3] * i1);
    }
}

// ---------------------------------------------------------------------------
extern "C" void kernel_launch(void* const* d_in, const int* in_sizes, int n_in,
                              void* d_out, int out_size)
{
    const float* x     = (const float*)d_in[0];
    const float* w_qkv = (const float*)d_in[1];
    const float* w_out = (const float*)d_in[2];
    float*       out   = (float*)d_out;

    __half *xh, *qkvh, *ah, *wq, *wo;
    cudaGetSymbolAddress((void**)&xh, g_xh);
    cudaGetSymbolAddress((void**)&qkvh, g_qkvh);
    cudaGetSymbolAddress((void**)&ah, g_ah);
    cudaGetSymbolAddress((void**)&wq, g_wq);
    cudaGetSymbolAddress((void**)&wo, g_wo);

    cudaFuncSetAttribute(gemm_mma, cudaFuncAttributeMaxDynamicSharedMemorySize, GSMEM);
    cudaFuncSetAttribute(swa_mma, cudaFuncAttributeMaxDynamicSharedMemorySize, ASMEM);

    const int nv8 = MTOK * DMODEL / 8;
    conv_half<<<(nv8 + 255) / 256, 256>>>((const float4*)x, (uint4*)xh, nv8);
    tr_half<<<dim3(QKVC / 32, DMODEL / 32), dim3(32, 8)>>>(w_qkv, wq, DMODEL, QKVC, DMODEL);
    tr_half<<<dim3(DMODEL / 32, DMODEL / 32), dim3(32, 8)>>>(w_out, wo, DMODEL, DMODEL, 0);

    gemm_mma<<<dim3(QKVC / 128, MTOK / 128), 256, GSMEM>>>(
        xh, wq, nullptr, qkvh, MTOK, QKVC, DMODEL);
    swa_mma<<<dim3(NSEQ / 128, BPAR * NH), 256, ASMEM>>>(qkvh, ah);
    gemm_mma<<<dim3(DMODEL / 128, MTOK / 128), 256, GSMEM>>>(
        ah, wo, out, nullptr, MTOK, DMODEL, DMODEL);
}

// round 14
// speedup vs baseline: 1.6132x; 1.0172x over previous
#include <cuda_runtime.h>
#include <cuda_fp16.h>
#include <math.h>

#define BPAR   4
#define NSEQ   4096
#define DMODEL 1024
#define NH     16
#define DH     64
#define WIN    256
#define MTOK   (BPAR * NSEQ)     /* 16384 */
#define QKVC   (3 * NH * DH)     /* 3072  */

// Scratch (allocation-free rule: __device__ globals)
__device__ __half g_xh[(size_t)MTOK * DMODEL];
__device__ __half g_qkvh[(size_t)MTOK * QKVC];
__device__ __half g_ah[(size_t)MTOK * DMODEL];
__device__ __half g_wq[(size_t)QKVC * DMODEL];   // w_qkv^T fp16 [N][K]
__device__ __half g_wo[(size_t)DMODEL * DMODEL]; // w_out^T fp16 [N][K]

// ---------------------------------------------------------------------------
__device__ __forceinline__ unsigned smem_u32(const void* p) {
    unsigned a;
    asm("{ .reg .u64 t; cvta.to.shared.u64 t, %1; cvt.u32.u64 %0, t; }"
        : "=r"(a) : "l"(p));
    return a;
}
__device__ __forceinline__ unsigned pkh(float x, float y) {
    __half2 hh = __floats2half2_rn(x, y);
    return *reinterpret_cast<unsigned*>(&hh);
}
__device__ __forceinline__ void mma16816(
    float& c0, float& c1, float& c2, float& c3,
    unsigned a0, unsigned a1, unsigned a2, unsigned a3,
    unsigned b0, unsigned b1) {
    asm volatile(
        "mma.sync.aligned.m16n8k16.row.col.f32.f16.f16.f32 "
        "{%0,%1,%2,%3},{%4,%5,%6,%7},{%8,%9},{%0,%1,%2,%3};"
        : "+f"(c0), "+f"(c1), "+f"(c2), "+f"(c3)
        : "r"(a0), "r"(a1), "r"(a2), "r"(a3), "r"(b0), "r"(b1));
}
__device__ __forceinline__ void cp16(unsigned saddr, const void* g) {
    asm volatile("cp.async.cg.shared.global [%0], [%1], 16;"
                 :: "r"(saddr), "l"(g) : "memory");
}
#define LDSM4(r, a)                                                           \
    asm volatile("ldmatrix.sync.aligned.m8n8.x4.shared.b16 {%0,%1,%2,%3},[%4];" \
                 : "=r"((r)[0]), "=r"((r)[1]), "=r"((r)[2]), "=r"((r)[3])     \
                 : "r"(a))
#define LDSM4T(r, a)                                                          \
    asm volatile("ldmatrix.sync.aligned.m8n8.x4.trans.shared.b16 {%0,%1,%2,%3},[%4];" \
                 : "=r"((r)[0]), "=r"((r)[1]), "=r"((r)[2]), "=r"((r)[3])     \
                 : "r"(a))

// ---------------------------------------------------------------------------
// prepass: elementwise fp32 -> fp16 (single plane)
// ---------------------------------------------------------------------------
__global__ __launch_bounds__(256) void conv_half(
    const float4* __restrict__ src, uint4* __restrict__ dst, int nvec8)
{
    int i = blockIdx.x * 256 + threadIdx.x;
    if (i >= nvec8) return;
    float4 f0 = src[2 * i], f1 = src[2 * i + 1];
    uint4 h;
    h.x = pkh(f0.x, f0.y); h.y = pkh(f0.z, f0.w);
    h.z = pkh(f1.x, f1.y); h.w = pkh(f1.z, f1.w);
    dst[i] = h;
}
// prepass: transpose + fp16 round, src [K][N] fp32 -> [N][K] fp16.
// columns n < nscale scaled by 0.125 (exact pow2; folds q-scale into W).
__global__ void tr_half(const float* __restrict__ src,
                        __half* __restrict__ dst, int K, int N, int nscale)
{
    __shared__ float tile[32][33];
    const int n0 = blockIdx.x * 32, k0 = blockIdx.y * 32;
    const int tx = threadIdx.x, ty = threadIdx.y;
    #pragma unroll
    for (int j = ty; j < 32; j += 8)
        tile[j][tx] = src[(size_t)(k0 + j) * N + n0 + tx];
    __syncthreads();
    #pragma unroll
    for (int j = ty; j < 32; j += 8) {
        float sc = (n0 + j < nscale) ? 0.125f : 1.0f;
        dst[(size_t)(n0 + j) * K + k0 + tx] = __float2half_rn(tile[tx][j] * sc);
    }
}

// ---------------------------------------------------------------------------
// 1-term fp16 HMMA GEMM, 4-stage cp.async, SINGLE barrier per chunk.
// Loads are issued AFTER the barrier into the just-retired stage, so no
// tail barrier is needed and each load has up to 3 compute phases of cover.
// A [M][K] fp16, B [N][K] fp16. Out: fp32 Cf OR fp16 Ch.
// 128x128 CTA tile, 256 thr (2x4 warps -> 64x32 warp tile), K chunk 32.
// ---------------------------------------------------------------------------
#define TILE_B 10240
#define STG_B  20480
#define NSTG   4
#define GSMEM  (NSTG * STG_B)

__device__ __forceinline__ void gload(
    unsigned sb, int st, int tid,
    const __half* a, const __half* b, int K, int k0)
{
    const __half* base[2] = {a, b};
    const int rlo = tid >> 2;
    const int pel = (tid & 3) << 3;
    const int pby = (tid & 3) << 4;
    #pragma unroll
    for (int i = 0; i < 4; i++) {
        const int tl  = i >> 1;
        const int row = ((i & 1) << 6) + rlo;
        cp16(sb + st * STG_B + tl * TILE_B + row * 80 + pby,
             base[tl] + (size_t)row * K + k0 + pel);
    }
    asm volatile("cp.async.commit_group;" ::: "memory");
}

__global__ __launch_bounds__(256, 2) void gemm_mma(
    const __half* __restrict__ A, const __half* __restrict__ B,
    float* __restrict__ Cf, __half* __restrict__ Ch, int M, int N, int K)
{
    extern __shared__ char dsm[];
    const unsigned sb = smem_u32(dsm);

    const int tid = threadIdx.x;
    const int wid = tid >> 5, lid = tid & 31;
    const int g = lid >> 2, t = lid & 3;
    const int wm = (wid >> 2) * 64;
    const int wn = (wid & 3) * 32;
    const int m0 = blockIdx.y * 128, n0 = blockIdx.x * 128;

    const __half* a_p = A + (size_t)m0 * K;
    const __half* b_p = B + (size_t)n0 * K;

    float acc[4][4][4];
    #pragma unroll
    for (int i = 0; i < 4; i++)
        #pragma unroll
        for (int j = 0; j < 4; j++)
            #pragma unroll
            for (int e = 0; e < 4; e++) acc[i][j][e] = 0.f;

    const int nk = K >> 5;   // 32 for K=1024
    gload(sb, 0, tid, a_p, b_p, K, 0);
    gload(sb, 1, tid, a_p, b_p, K, 32);
    gload(sb, 2, tid, a_p, b_p, K, 64);

    for (int kc = 0; kc < nk; kc++) {
        // ensure stage kc's group is complete (outstanding <= newest 2)
        const int rem = nk - 1 - kc;
        if (rem >= 2)      asm volatile("cp.async.wait_group 2;" ::: "memory");
        else if (rem == 1) asm volatile("cp.async.wait_group 1;" ::: "memory");
        else               asm volatile("cp.async.wait_group 0;" ::: "memory");
        __syncthreads();   // all warps see stage kc AND are done with stage kc-1

        // refill the just-retired stage ((kc+3)%4 == (kc-1)%4)
        if (kc + 3 < nk)
            gload(sb, (kc + 3) & 3, tid, a_p, b_p, K, (kc + 3) << 5);

        const int st = kc & 3;
        const unsigned* pA = reinterpret_cast<const unsigned*>(dsm + st * STG_B);
        const unsigned* pB = pA + 2560;

        #pragma unroll
        for (int s = 0; s < 2; s++) {
            const int w = s * 8 + t;
            unsigned a[4][4];
            #pragma unroll
            for (int tm = 0; tm < 4; tm++) {
                const int r0 = (wm + tm * 16 + g) * 20;
                const int r1 = r0 + 8 * 20;
                a[tm][0] = pA[r0 + w];     a[tm][1] = pA[r1 + w];
                a[tm][2] = pA[r0 + w + 4]; a[tm][3] = pA[r1 + w + 4];
            }
            #pragma unroll
            for (int tn = 0; tn < 4; tn++) {
                const int nr = (wn + tn * 8 + g) * 20;
                const unsigned b0 = pB[nr + w], b1 = pB[nr + w + 4];
                #pragma unroll
                for (int tm = 0; tm < 4; tm++) {
                    float* c = acc[tm][tn];
                    mma16816(c[0], c[1], c[2], c[3],
                             a[tm][0], a[tm][1], a[tm][2], a[tm][3], b0, b1);
                }
            }
        }
        // no tail barrier: next iteration's barrier protects stage reuse
    }

    #pragma unroll
    for (int tm = 0; tm < 4; tm++) {
        #pragma unroll
        for (int tn = 0; tn < 4; tn++) {
            float* c = acc[tm][tn];
            size_t r0 = (size_t)(m0 + wm + tm * 16 + g) * N + n0 + wn + tn * 8 + 2 * t;
            if (Cf) {
                *reinterpret_cast<float2*>(Cf + r0)                 = make_float2(c[0], c[1]);
                *reinterpret_cast<float2*>(Cf + r0 + 8 * (size_t)N) = make_float2(c[2], c[3]);
            } else {
                *reinterpret_cast<unsigned*>(Ch + r0) = pkh(c[0], c[1]);
                *reinterpret_cast<unsigned*>(Ch + r0 + 8 * (size_t)N) = pkh(c[2], c[3]);
            }
        }
    }
}

// ---------------------------------------------------------------------------
// fp16 HMMA sliding-window attention (unchanged, proven config).
// grid = (32, 64), 256 thr, occupancy 2. Q/K/V single fp16 plane.
// ---------------------------------------------------------------------------
#define RB    144
#define QPL   18432
#define ASMEM (5 * QPL)

__global__ __launch_bounds__(256, 2) void swa_mma(
    const __half* __restrict__ qkvh, __half* __restrict__ oh)
{
    extern __shared__ char sm[];
    const unsigned sb = smem_u32(sm);
    const int blkq = blockIdx.x;
    const int bh = blockIdx.y, b = bh >> 4, hh = bh & 15;
    const int tid = threadIdx.x, w = tid >> 5, lid = tid & 31;
    const int g = lid >> 2, t = lid & 3;
    const int q0 = blkq * 128;
    const size_t tokb = (size_t)b * NSEQ;

    const unsigned sQ = sb;
    const unsigned sK = sb + QPL;
    const unsigned sV = sb + 3 * QPL;

    {
        int r = tid >> 1;
        const __half* src = qkvh + (tokb + q0 + r) * QKVC + hh * DH + (tid & 1) * 32;
        unsigned dst = sQ + r * RB + (tid & 1) * 64;
        #pragma unroll
        for (int s = 0; s < 4; s++) cp16(dst + s * 16, src + s * 8);
    }
    asm volatile("cp.async.commit_group;" ::: "memory");

    const int cstart = (q0 >= 256) ? 0 : (q0 >= 128 ? 1 : 2);

    auto ldkv = [&](int c, int st) {
        const int kb = q0 - 256 + c * 128;
        const int r = tid & 127;
        const int isv = tid >> 7;
        const size_t row = tokb + kb + r;
        const int off = (isv ? 2 * DMODEL : DMODEL) + hh * DH;
        const __half* sh = qkvh + row * QKVC + off;
        unsigned base = (isv ? sV : sK) + st * QPL + r * RB;
        #pragma unroll
        for (int s = 0; s < 8; s++) cp16(base + s * 16, sh + s * 8);
        asm volatile("cp.async.commit_group;" ::: "memory");
    };

    ldkv(cstart, 0);
    asm volatile("cp.async.wait_group 0;" ::: "memory");
    __syncthreads();

    unsigned qh[4][4];
    {
        unsigned ab = sQ + (w * 16 + (lid & 15)) * RB + (lid >> 4) * 16;
        #pragma unroll
        for (int ks = 0; ks < 4; ks++) LDSM4(qh[ks], ab + ks * 32);
    }

    float O[8][4];
    #pragma unroll
    for (int i = 0; i < 8; i++)
        #pragma unroll
        for (int e = 0; e < 4; e++) O[i][e] = 0.f;
    float m0 = -1e30f, m1 = -1e30f, l0 = 0.f, l1 = 0.f;
    const int qi0 = q0 + w * 16 + g, qi1 = qi0 + 8;

    const unsigned klane = (lid & 7) * RB + (lid >> 3) * 16;
    const unsigned vlane = (lid & 15) * RB + (lid >> 4) * 16;

    for (int c = cstart; c <= 2; ++c) {
        const int st = (c - cstart) & 1;
        if (c < 2) ldkv(c + 1, st ^ 1);

        const int kb = q0 - 256 + c * 128;
        const int tnlo = (c == 0) ? 2 * w : 0;
        const int tnhi = (c == 2) ? 2 * w + 1 : 15;
        const int jlo = (c == 0) ? w : 0;
        const int jhi = (c == 2) ? w : 7;
        const unsigned kbase = sK + st * QPL + klane;
        const unsigned vbase = sV + st * QPL + vlane;

        #pragma unroll
        for (int hf = 0; hf < 2; hf++) {
            const int lo  = (tnlo > hf * 8) ? tnlo : hf * 8;
            const int hi2 = (tnhi < hf * 8 + 7) ? tnhi : hf * 8 + 7;
            if (lo > hi2) continue;

            float S[8][4];
            #pragma unroll
            for (int i = 0; i < 8; i++) {
                const int tt = hf * 8 + i;
                if (tt < lo || tt > hi2) continue;
                S[i][0] = S[i][1] = S[i][2] = S[i][3] = 0.f;
                #pragma unroll
                for (int sp = 0; sp < 2; sp++) {
                    unsigned kh[4];
                    LDSM4(kh, kbase + tt * (8 * RB) + sp * 64);
                    float* c4 = S[i];
                    mma16816(c4[0], c4[1], c4[2], c4[3],
                             qh[2*sp][0], qh[2*sp][1], qh[2*sp][2], qh[2*sp][3], kh[0], kh[1]);
                    mma16816(c4[0], c4[1], c4[2], c4[3],
                             qh[2*sp+1][0], qh[2*sp+1][1], qh[2*sp+1][2], qh[2*sp+1][3], kh[2], kh[3]);
                }
            }

            float cm0 = -1e30f, cm1 = -1e30f;
            #pragma unroll
            for (int i = 0; i < 8; i++) {
                const int tt = hf * 8 + i;
                if (tt < lo || tt > hi2) continue;
                const int k0c = kb + tt * 8 + 2 * t;
                if (c == 0) {
                    if (k0c     < qi0 - 255) S[i][0] = -1e30f;
                    if (k0c + 1 < qi0 - 255) S[i][1] = -1e30f;
                    if (k0c     < qi1 - 255) S[i][2] = -1e30f;
                    if (k0c + 1 < qi1 - 255) S[i][3] = -1e30f;
                } else if (c == 2) {
                    if (k0c     > qi0) S[i][0] = -1e30f;
                    if (k0c + 1 > qi0) S[i][1] = -1e30f;
                    if (k0c     > qi1) S[i][2] = -1e30f;
                    if (k0c + 1 > qi1) S[i][3] = -1e30f;
                }
                cm0 = fmaxf(cm0, fmaxf(S[i][0], S[i][1]));
                cm1 = fmaxf(cm1, fmaxf(S[i][2], S[i][3]));
            }
            cm0 = fmaxf(cm0, __shfl_xor_sync(0xFFFFFFFFu, cm0, 1));
            cm0 = fmaxf(cm0, __shfl_xor_sync(0xFFFFFFFFu, cm0, 2));
            cm1 = fmaxf(cm1, __shfl_xor_sync(0xFFFFFFFFu, cm1, 1));
            cm1 = fmaxf(cm1, __shfl_xor_sync(0xFFFFFFFFu, cm1, 2));
            const float mn0 = fmaxf(m0, cm0), mn1 = fmaxf(m1, cm1);
            const float corr0 = __expf(m0 - mn0), corr1 = __expf(m1 - mn1);
            m0 = mn0; m1 = mn1;

            float ls0 = 0.f, ls1 = 0.f;
            #pragma unroll
            for (int i = 0; i < 8; i++) {
                const int tt = hf * 8 + i;
                if (tt < lo || tt > hi2) continue;
                S[i][0] = __expf(S[i][0] - m0);
                S[i][1] = __expf(S[i][1] - m0);
                S[i][2] = __expf(S[i][2] - m1);
                S[i][3] = __expf(S[i][3] - m1);
                ls0 += S[i][0] + S[i][1];
                ls1 += S[i][2] + S[i][3];
            }
            l0 = l0 * corr0 + ls0;
            l1 = l1 * corr1 + ls1;
            #pragma unroll
            for (int i = 0; i < 8; i++) {
                O[i][0] *= corr0; O[i][1] *= corr0;
                O[i][2] *= corr1; O[i][3] *= corr1;
            }

            #pragma unroll
            for (int j = 0; j < 4; j++) {
                const int jj2 = hf * 4 + j;
                if (jj2 < jlo || jj2 > jhi) continue;
                unsigned ph[4];
                ph[0] = pkh(S[2*j][0],   S[2*j][1]);
                ph[1] = pkh(S[2*j][2],   S[2*j][3]);
                ph[2] = pkh(S[2*j+1][0], S[2*j+1][1]);
                ph[3] = pkh(S[2*j+1][2], S[2*j+1][3]);
                #pragma unroll
                for (int tp = 0; tp < 4; tp++) {
                    unsigned vh[4];
                    LDSM4T(vh, vbase + jj2 * (16 * RB) + tp * 32);
                    float* cA = O[2 * tp];
                    float* cB = O[2 * tp + 1];
                    mma16816(cA[0], cA[1], cA[2], cA[3],
                             ph[0], ph[1], ph[2], ph[3], vh[0], vh[1]);
                    mma16816(cB[0], cB[1], cB[2], cB[3],
                             ph[0], ph[1], ph[2], ph[3], vh[2], vh[3]);
                }
            }
        }

        if (c < 2) asm volatile("cp.async.wait_group 0;" ::: "memory");
        __syncthreads();
    }

    l0 += __shfl_xor_sync(0xFFFFFFFFu, l0, 1);
    l0 += __shfl_xor_sync(0xFFFFFFFFu, l0, 2);
    l1 += __shfl_xor_sync(0xFFFFFFFFu, l1, 1);
    l1 += __shfl_xor_sync(0xFFFFFFFFu, l1, 2);
    const float i0 = 1.f / l0, i1 = 1.f / l1;
    const size_t t0 = (tokb + q0 + w * 16 + g) * DMODEL + hh * DH;
    const size_t t1 = t0 + 8 * DMODEL;
    #pragma unroll
    for (int tp = 0; tp < 8; tp++) {
        const int col = tp * 8 + 2 * t;
        *reinterpret_cast<unsigned*>(oh + t0 + col) = pkh(O[tp][0] * i0, O[tp][1] * i0);
        *reinterpret_cast<unsigned*>(oh + t1 + col) = pkh(O[tp][2] * i1, O[tp][3] * i1);
    }
}

// ---------------------------------------------------------------------------
extern "C" void kernel_launch(void* const* d_in, const int* in_sizes, int n_in,
                              void* d_out, int out_size)
{
    const float* x     = (const float*)d_in[0];
    const float* w_qkv = (const float*)d_in[1];
    const float* w_out = (const float*)d_in[2];
    float*       out   = (float*)d_out;

    __half *xh, *qkvh, *ah, *wq, *wo;
    cudaGetSymbolAddress((void**)&xh, g_xh);
    cudaGetSymbolAddress((void**)&qkvh, g_qkvh);
    cudaGetSymbolAddress((void**)&ah, g_ah);
    cudaGetSymbolAddress((void**)&wq, g_wq);
    cudaGetSymbolAddress((void**)&wo, g_wo);

    cudaFuncSetAttribute(gemm_mma, cudaFuncAttributeMaxDynamicSharedMemorySize, GSMEM);
    cudaFuncSetAttribute(swa_mma, cudaFuncAttributeMaxDynamicSharedMemorySize, ASMEM);

    const int nv8 = MTOK * DMODEL / 8;
    conv_half<<<(nv8 + 255) / 256, 256>>>((const float4*)x, (uint4*)xh, nv8);
    tr_half<<<dim3(QKVC / 32, DMODEL / 32), dim3(32, 8)>>>(w_qkv, wq, DMODEL, QKVC, DMODEL);
    tr_half<<<dim3(DMODEL / 32, DMODEL / 32), dim3(32, 8)>>>(w_out, wo, DMODEL, DMODEL, 0);

    gemm_mma<<<dim3(QKVC / 128, MTOK / 128), 256, GSMEM>>>(
        xh, wq, nullptr, qkvh, MTOK, QKVC, DMODEL);
    swa_mma<<<dim3(NSEQ / 128, BPAR * NH), 256, ASMEM>>>(qkvh, ah);
    gemm_mma<<<dim3(DMODEL / 128, MTOK / 128), 256, GSMEM>>>(
        ah, wo, out, nullptr, MTOK, DMODEL, DMODEL);
}

// round 15
// speedup vs baseline: 1.6867x; 1.0455x over previous
#include <cuda_runtime.h>
#include <cuda_fp16.h>
#include <math.h>

#define BPAR   4
#define NSEQ   4096
#define DMODEL 1024
#define NH     16
#define DH     64
#define WIN    256
#define MTOK   (BPAR * NSEQ)     /* 16384 */
#define QKVC   (3 * NH * DH)     /* 3072  */

// Scratch (allocation-free rule: __device__ globals)
__device__ __half g_xh[(size_t)MTOK * DMODEL];
__device__ __half g_qkvh[(size_t)MTOK * QKVC];
__device__ __half g_ah[(size_t)MTOK * DMODEL];
__device__ __half g_wq[(size_t)QKVC * DMODEL];   // w_qkv^T fp16 [N][K]
__device__ __half g_wo[(size_t)DMODEL * DMODEL]; // w_out^T fp16 [N][K]

// ---------------------------------------------------------------------------
__device__ __forceinline__ unsigned smem_u32(const void* p) {
    unsigned a;
    asm("{ .reg .u64 t; cvta.to.shared.u64 t, %1; cvt.u32.u64 %0, t; }"
        : "=r"(a) : "l"(p));
    return a;
}
__device__ __forceinline__ unsigned pkh(float x, float y) {
    __half2 hh = __floats2half2_rn(x, y);
    return *reinterpret_cast<unsigned*>(&hh);
}
__device__ __forceinline__ void mma16816(
    float& c0, float& c1, float& c2, float& c3,
    unsigned a0, unsigned a1, unsigned a2, unsigned a3,
    unsigned b0, unsigned b1) {
    asm volatile(
        "mma.sync.aligned.m16n8k16.row.col.f32.f16.f16.f32 "
        "{%0,%1,%2,%3},{%4,%5,%6,%7},{%8,%9},{%0,%1,%2,%3};"
        : "+f"(c0), "+f"(c1), "+f"(c2), "+f"(c3)
        : "r"(a0), "r"(a1), "r"(a2), "r"(a3), "r"(b0), "r"(b1));
}
__device__ __forceinline__ void cp16(unsigned saddr, const void* g) {
    asm volatile("cp.async.cg.shared.global [%0], [%1], 16;"
                 :: "r"(saddr), "l"(g) : "memory");
}
#define LDSM4(r, a)                                                           \
    asm volatile("ldmatrix.sync.aligned.m8n8.x4.shared.b16 {%0,%1,%2,%3},[%4];" \
                 : "=r"((r)[0]), "=r"((r)[1]), "=r"((r)[2]), "=r"((r)[3])     \
                 : "r"(a))
#define LDSM4T(r, a)                                                          \
    asm volatile("ldmatrix.sync.aligned.m8n8.x4.trans.shared.b16 {%0,%1,%2,%3},[%4];" \
                 : "=r"((r)[0]), "=r"((r)[1]), "=r"((r)[2]), "=r"((r)[3])     \
                 : "r"(a))

// ---------------------------------------------------------------------------
// prepass: elementwise fp32 -> fp16 (single plane)
// ---------------------------------------------------------------------------
__global__ __launch_bounds__(256) void conv_half(
    const float4* __restrict__ src, uint4* __restrict__ dst, int nvec8)
{
    int i = blockIdx.x * 256 + threadIdx.x;
    if (i >= nvec8) return;
    float4 f0 = src[2 * i], f1 = src[2 * i + 1];
    uint4 h;
    h.x = pkh(f0.x, f0.y); h.y = pkh(f0.z, f0.w);
    h.z = pkh(f1.x, f1.y); h.w = pkh(f1.z, f1.w);
    dst[i] = h;
}
// prepass: transpose + fp16 round, src [K][N] fp32 -> [N][K] fp16.
// columns n < nscale scaled by 0.125 (exact pow2; folds q-scale into W).
__global__ void tr_half(const float* __restrict__ src,
                        __half* __restrict__ dst, int K, int N, int nscale)
{
    __shared__ float tile[32][33];
    const int n0 = blockIdx.x * 32, k0 = blockIdx.y * 32;
    const int tx = threadIdx.x, ty = threadIdx.y;
    #pragma unroll
    for (int j = ty; j < 32; j += 8)
        tile[j][tx] = src[(size_t)(k0 + j) * N + n0 + tx];
    __syncthreads();
    #pragma unroll
    for (int j = ty; j < 32; j += 8) {
        float sc = (n0 + j < nscale) ? 0.125f : 1.0f;
        dst[(size_t)(n0 + j) * K + k0 + tx] = __float2half_rn(tile[tx][j] * sc);
    }
}

// ---------------------------------------------------------------------------
// 1-term fp16 HMMA GEMM, 4-stage cp.async, single barrier per chunk,
// ldmatrix fragment loads (12 LDSM4 per warp-chunk instead of 48 LDS.32).
// A [M][K] fp16, B [N][K] fp16. Out: fp32 Cf OR fp16 Ch.
// 128x128 CTA tile, 256 thr (2x4 warps -> 64x32 warp tile), K chunk 32.
// ---------------------------------------------------------------------------
#define TILE_B 10240
#define STG_B  20480
#define NSTG   4
#define GSMEM  (NSTG * STG_B)

__device__ __forceinline__ void gload(
    unsigned sb, int st, int tid,
    const __half* a, const __half* b, int K, int k0)
{
    const __half* base[2] = {a, b};
    const int rlo = tid >> 2;
    const int pel = (tid & 3) << 3;
    const int pby = (tid & 3) << 4;
    #pragma unroll
    for (int i = 0; i < 4; i++) {
        const int tl  = i >> 1;
        const int row = ((i & 1) << 6) + rlo;
        cp16(sb + st * STG_B + tl * TILE_B + row * 80 + pby,
             base[tl] + (size_t)row * K + k0 + pel);
    }
    asm volatile("cp.async.commit_group;" ::: "memory");
}

__global__ __launch_bounds__(256, 2) void gemm_mma(
    const __half* __restrict__ A, const __half* __restrict__ B,
    float* __restrict__ Cf, __half* __restrict__ Ch, int M, int N, int K)
{
    extern __shared__ char dsm[];
    const unsigned sb = smem_u32(dsm);

    const int tid = threadIdx.x;
    const int wid = tid >> 5, lid = tid & 31;
    const int g = lid >> 2, t = lid & 3;
    const int wm = (wid >> 2) * 64;
    const int wn = (wid & 3) * 32;
    const int m0 = blockIdx.y * 128, n0 = blockIdx.x * 128;

    const __half* a_p = A + (size_t)m0 * K;
    const __half* b_p = B + (size_t)n0 * K;

    // ldmatrix lane offsets (within a stage)
    // A tile (tm, s): rows wm+tm*16+(lid&7)+((lid>>3)&1)*8, byte s*32+(lid>>4)*16
    const unsigned aoff =
        (unsigned)((wm + (lid & 7) + ((lid >> 3) & 1) * 8) * 80 + (lid >> 4) * 16);
    // B tile (tn): rows wn+tn*8+(lid&7), byte (lid>>3)*16  -> {b0s0,b1s0,b0s1,b1s1}
    const unsigned boff =
        (unsigned)(TILE_B + (wn + (lid & 7)) * 80 + (lid >> 3) * 16);

    float acc[4][4][4];
    #pragma unroll
    for (int i = 0; i < 4; i++)
        #pragma unroll
        for (int j = 0; j < 4; j++)
            #pragma unroll
            for (int e = 0; e < 4; e++) acc[i][j][e] = 0.f;

    const int nk = K >> 5;   // 32 for K=1024
    gload(sb, 0, tid, a_p, b_p, K, 0);
    gload(sb, 1, tid, a_p, b_p, K, 32);
    gload(sb, 2, tid, a_p, b_p, K, 64);

    for (int kc = 0; kc < nk; kc++) {
        const int rem = nk - 1 - kc;
        if (rem >= 2)      asm volatile("cp.async.wait_group 2;" ::: "memory");
        else if (rem == 1) asm volatile("cp.async.wait_group 1;" ::: "memory");
        else               asm volatile("cp.async.wait_group 0;" ::: "memory");
        __syncthreads();

        if (kc + 3 < nk)
            gload(sb, (kc + 3) & 3, tid, a_p, b_p, K, (kc + 3) << 5);

        const unsigned stb = sb + (kc & 3) * STG_B;

        // B fragments for the whole chunk: one LDSM4 per tn
        unsigned bf[4][4];
        #pragma unroll
        for (int tn = 0; tn < 4; tn++)
            LDSM4(bf[tn], stb + boff + tn * (8 * 80));

        #pragma unroll
        for (int s = 0; s < 2; s++) {
            unsigned a[4][4];
            #pragma unroll
            for (int tm = 0; tm < 4; tm++)
                LDSM4(a[tm], stb + aoff + tm * (16 * 80) + s * 32);
            #pragma unroll
            for (int tn = 0; tn < 4; tn++) {
                const unsigned b0 = bf[tn][2 * s], b1 = bf[tn][2 * s + 1];
                #pragma unroll
                for (int tm = 0; tm < 4; tm++) {
                    float* c = acc[tm][tn];
                    mma16816(c[0], c[1], c[2], c[3],
                             a[tm][0], a[tm][1], a[tm][2], a[tm][3], b0, b1);
                }
            }
        }
        // no tail barrier: next iteration's barrier protects stage reuse
    }

    #pragma unroll
    for (int tm = 0; tm < 4; tm++) {
        #pragma unroll
        for (int tn = 0; tn < 4; tn++) {
            float* c = acc[tm][tn];
            size_t r0 = (size_t)(m0 + wm + tm * 16 + g) * N + n0 + wn + tn * 8 + 2 * t;
            if (Cf) {
                *reinterpret_cast<float2*>(Cf + r0)                 = make_float2(c[0], c[1]);
                *reinterpret_cast<float2*>(Cf + r0 + 8 * (size_t)N) = make_float2(c[2], c[3]);
            } else {
                *reinterpret_cast<unsigned*>(Ch + r0) = pkh(c[0], c[1]);
                *reinterpret_cast<unsigned*>(Ch + r0 + 8 * (size_t)N) = pkh(c[2], c[3]);
            }
        }
    }
}

// ---------------------------------------------------------------------------
// fp16 HMMA sliding-window attention (unchanged, proven config).
// grid = (32, 64), 256 thr, occupancy 2. Q/K/V single fp16 plane.
// ---------------------------------------------------------------------------
#define RB    144
#define QPL   18432
#define ASMEM (5 * QPL)

__global__ __launch_bounds__(256, 2) void swa_mma(
    const __half* __restrict__ qkvh, __half* __restrict__ oh)
{
    extern __shared__ char sm[];
    const unsigned sb = smem_u32(sm);
    const int blkq = blockIdx.x;
    const int bh = blockIdx.y, b = bh >> 4, hh = bh & 15;
    const int tid = threadIdx.x, w = tid >> 5, lid = tid & 31;
    const int g = lid >> 2, t = lid & 3;
    const int q0 = blkq * 128;
    const size_t tokb = (size_t)b * NSEQ;

    const unsigned sQ = sb;
    const unsigned sK = sb + QPL;
    const unsigned sV = sb + 3 * QPL;

    {
        int r = tid >> 1;
        const __half* src = qkvh + (tokb + q0 + r) * QKVC + hh * DH + (tid & 1) * 32;
        unsigned dst = sQ + r * RB + (tid & 1) * 64;
        #pragma unroll
        for (int s = 0; s < 4; s++) cp16(dst + s * 16, src + s * 8);
    }
    asm volatile("cp.async.commit_group;" ::: "memory");

    const int cstart = (q0 >= 256) ? 0 : (q0 >= 128 ? 1 : 2);

    auto ldkv = [&](int c, int st) {
        const int kb = q0 - 256 + c * 128;
        const int r = tid & 127;
        const int isv = tid >> 7;
        const size_t row = tokb + kb + r;
        const int off = (isv ? 2 * DMODEL : DMODEL) + hh * DH;
        const __half* sh = qkvh + row * QKVC + off;
        unsigned base = (isv ? sV : sK) + st * QPL + r * RB;
        #pragma unroll
        for (int s = 0; s < 8; s++) cp16(base + s * 16, sh + s * 8);
        asm volatile("cp.async.commit_group;" ::: "memory");
    };

    ldkv(cstart, 0);
    asm volatile("cp.async.wait_group 0;" ::: "memory");
    __syncthreads();

    unsigned qh[4][4];
    {
        unsigned ab = sQ + (w * 16 + (lid & 15)) * RB + (lid >> 4) * 16;
        #pragma unroll
        for (int ks = 0; ks < 4; ks++) LDSM4(qh[ks], ab + ks * 32);
    }

    float O[8][4];
    #pragma unroll
    for (int i = 0; i < 8; i++)
        #pragma unroll
        for (int e = 0; e < 4; e++) O[i][e] = 0.f;
    float m0 = -1e30f, m1 = -1e30f, l0 = 0.f, l1 = 0.f;
    const int qi0 = q0 + w * 16 + g, qi1 = qi0 + 8;

    const unsigned klane = (lid & 7) * RB + (lid >> 3) * 16;
    const unsigned vlane = (lid & 15) * RB + (lid >> 4) * 16;

    for (int c = cstart; c <= 2; ++c) {
        const int st = (c - cstart) & 1;
        if (c < 2) ldkv(c + 1, st ^ 1);

        const int kb = q0 - 256 + c * 128;
        const int tnlo = (c == 0) ? 2 * w : 0;
        const int tnhi = (c == 2) ? 2 * w + 1 : 15;
        const int jlo = (c == 0) ? w : 0;
        const int jhi = (c == 2) ? w : 7;
        const unsigned kbase = sK + st * QPL + klane;
        const unsigned vbase = sV + st * QPL + vlane;

        #pragma unroll
        for (int hf = 0; hf < 2; hf++) {
            const int lo  = (tnlo > hf * 8) ? tnlo : hf * 8;
            const int hi2 = (tnhi < hf * 8 + 7) ? tnhi : hf * 8 + 7;
            if (lo > hi2) continue;

            float S[8][4];
            #pragma unroll
            for (int i = 0; i < 8; i++) {
                const int tt = hf * 8 + i;
                if (tt < lo || tt > hi2) continue;
                S[i][0] = S[i][1] = S[i][2] = S[i][3] = 0.f;
                #pragma unroll
                for (int sp = 0; sp < 2; sp++) {
                    unsigned kh[4];
                    LDSM4(kh, kbase + tt * (8 * RB) + sp * 64);
                    float* c4 = S[i];
                    mma16816(c4[0], c4[1], c4[2], c4[3],
                             qh[2*sp][0], qh[2*sp][1], qh[2*sp][2], qh[2*sp][3], kh[0], kh[1]);
                    mma16816(c4[0], c4[1], c4[2], c4[3],
                             qh[2*sp+1][0], qh[2*sp+1][1], qh[2*sp+1][2], qh[2*sp+1][3], kh[2], kh[3]);
                }
            }

            float cm0 = -1e30f, cm1 = -1e30f;
            #pragma unroll
            for (int i = 0; i < 8; i++) {
                const int tt = hf * 8 + i;
                if (tt < lo || tt > hi2) continue;
                const int k0c = kb + tt * 8 + 2 * t;
                if (c == 0) {
                    if (k0c     < qi0 - 255) S[i][0] = -1e30f;
                    if (k0c + 1 < qi0 - 255) S[i][1] = -1e30f;
                    if (k0c     < qi1 - 255) S[i][2] = -1e30f;
                    if (k0c + 1 < qi1 - 255) S[i][3] = -1e30f;
                } else if (c == 2) {
                    if (k0c     > qi0) S[i][0] = -1e30f;
                    if (k0c + 1 > qi0) S[i][1] = -1e30f;
                    if (k0c     > qi1) S[i][2] = -1e30f;
                    if (k0c + 1 > qi1) S[i][3] = -1e30f;
                }
                cm0 = fmaxf(cm0, fmaxf(S[i][0], S[i][1]));
                cm1 = fmaxf(cm1, fmaxf(S[i][2], S[i][3]));
            }
            cm0 = fmaxf(cm0, __shfl_xor_sync(0xFFFFFFFFu, cm0, 1));
            cm0 = fmaxf(cm0, __shfl_xor_sync(0xFFFFFFFFu, cm0, 2));
            cm1 = fmaxf(cm1, __shfl_xor_sync(0xFFFFFFFFu, cm1, 1));
            cm1 = fmaxf(cm1, __shfl_xor_sync(0xFFFFFFFFu, cm1, 2));
            const float mn0 = fmaxf(m0, cm0), mn1 = fmaxf(m1, cm1);
            const float corr0 = __expf(m0 - mn0), corr1 = __expf(m1 - mn1);
            m0 = mn0; m1 = mn1;

            float ls0 = 0.f, ls1 = 0.f;
            #pragma unroll
            for (int i = 0; i < 8; i++) {
                const int tt = hf * 8 + i;
                if (tt < lo || tt > hi2) continue;
                S[i][0] = __expf(S[i][0] - m0);
                S[i][1] = __expf(S[i][1] - m0);
                S[i][2] = __expf(S[i][2] - m1);
                S[i][3] = __expf(S[i][3] - m1);
                ls0 += S[i][0] + S[i][1];
                ls1 += S[i][2] + S[i][3];
            }
            l0 = l0 * corr0 + ls0;
            l1 = l1 * corr1 + ls1;
            #pragma unroll
            for (int i = 0; i < 8; i++) {
                O[i][0] *= corr0; O[i][1] *= corr0;
                O[i][2] *= corr1; O[i][3] *= corr1;
            }

            #pragma unroll
            for (int j = 0; j < 4; j++) {
                const int jj2 = hf * 4 + j;
                if (jj2 < jlo || jj2 > jhi) continue;
                unsigned ph[4];
                ph[0] = pkh(S[2*j][0],   S[2*j][1]);
                ph[1] = pkh(S[2*j][2],   S[2*j][3]);
                ph[2] = pkh(S[2*j+1][0], S[2*j+1][1]);
                ph[3] = pkh(S[2*j+1][2], S[2*j+1][3]);
                #pragma unroll
                for (int tp = 0; tp < 4; tp++) {
                    unsigned vh[4];
                    LDSM4T(vh, vbase + jj2 * (16 * RB) + tp * 32);
                    float* cA = O[2 * tp];
                    float* cB = O[2 * tp + 1];
                    mma16816(cA[0], cA[1], cA[2], cA[3],
                             ph[0], ph[1], ph[2], ph[3], vh[0], vh[1]);
                    mma16816(cB[0], cB[1], cB[2], cB[3],
                             ph[0], ph[1], ph[2], ph[3], vh[2], vh[3]);
                }
            }
        }

        if (c < 2) asm volatile("cp.async.wait_group 0;" ::: "memory");
        __syncthreads();
    }

    l0 += __shfl_xor_sync(0xFFFFFFFFu, l0, 1);
    l0 += __shfl_xor_sync(0xFFFFFFFFu, l0, 2);
    l1 += __shfl_xor_sync(0xFFFFFFFFu, l1, 1);
    l1 += __shfl_xor_sync(0xFFFFFFFFu, l1, 2);
    const float i0 = 1.f / l0, i1 = 1.f / l1;
    const size_t t0 = (tokb + q0 + w * 16 + g) * DMODEL + hh * DH;
    const size_t t1 = t0 + 8 * DMODEL;
    #pragma unroll
    for (int tp = 0; tp < 8; tp++) {
        const int col = tp * 8 + 2 * t;
        *reinterpret_cast<unsigned*>(oh + t0 + col) = pkh(O[tp][0] * i0, O[tp][1] * i0);
        *reinterpret_cast<unsigned*>(oh + t1 + col) = pkh(O[tp][2] * i1, O[tp][3] * i1);
    }
}

// ---------------------------------------------------------------------------
extern "C" void kernel_launch(void* const* d_in, const int* in_sizes, int n_in,
                              void* d_out, int out_size)
{
    const float* x     = (const float*)d_in[0];
    const float* w_qkv = (const float*)d_in[1];
    const float* w_out = (const float*)d_in[2];
    float*       out   = (float*)d_out;

    __half *xh, *qkvh, *ah, *wq, *wo;
    cudaGetSymbolAddress((void**)&xh, g_xh);
    cudaGetSymbolAddress((void**)&qkvh, g_qkvh);
    cudaGetSymbolAddress((void**)&ah, g_ah);
    cudaGetSymbolAddress((void**)&wq, g_wq);
    cudaGetSymbolAddress((void**)&wo, g_wo);

    cudaFuncSetAttribute(gemm_mma, cudaFuncAttributeMaxDynamicSharedMemorySize, GSMEM);
    cudaFuncSetAttribute(swa_mma, cudaFuncAttributeMaxDynamicSharedMemorySize, ASMEM);

    const int nv8 = MTOK * DMODEL / 8;
    conv_half<<<(nv8 + 255) / 256, 256>>>((const float4*)x, (uint4*)xh, nv8);
    tr_half<<<dim3(QKVC / 32, DMODEL / 32), dim3(32, 8)>>>(w_qkv, wq, DMODEL, QKVC, DMODEL);
    tr_half<<<dim3(DMODEL / 32, DMODEL / 32), dim3(32, 8)>>>(w_out, wo, DMODEL, DMODEL, 0);

    gemm_mma<<<dim3(QKVC / 128, MTOK / 128), 256, GSMEM>>>(
        xh, wq, nullptr, qkvh, MTOK, QKVC, DMODEL);
    swa_mma<<<dim3(NSEQ / 128, BPAR * NH), 256, ASMEM>>>(qkvh, ah);
    gemm_mma<<<dim3(DMODEL / 128, MTOK / 128), 256, GSMEM>>>(
        ah, wo, out, nullptr, MTOK, DMODEL, DMODEL);
}

// round 17
// speedup vs baseline: 1.6970x; 1.0061x over previous
#include <cuda_runtime.h>
#include <cuda_fp16.h>
#include <math.h>

#define BPAR   4
#define NSEQ   4096
#define DMODEL 1024
#define NH     16
#define DH     64
#define WIN    256
#define MTOK   (BPAR * NSEQ)     /* 16384 */
#define QKVC   (3 * NH * DH)     /* 3072  */

// Scratch (allocation-free rule: __device__ globals)
__device__ __half g_xh[(size_t)MTOK * DMODEL];
__device__ __half g_qkvh[(size_t)MTOK * QKVC];
__device__ __half g_ah[(size_t)MTOK * DMODEL];
__device__ __half g_wq[(size_t)QKVC * DMODEL];   // w_qkv^T fp16 [N][K]
__device__ __half g_wo[(size_t)DMODEL * DMODEL]; // w_out^T fp16 [N][K]

// ---------------------------------------------------------------------------
__device__ __forceinline__ unsigned smem_u32(const void* p) {
    unsigned a;
    asm("{ .reg .u64 t; cvta.to.shared.u64 t, %1; cvt.u32.u64 %0, t; }"
        : "=r"(a) : "l"(p));
    return a;
}
__device__ __forceinline__ unsigned pkh(float x, float y) {
    __half2 hh = __floats2half2_rn(x, y);
    return *reinterpret_cast<unsigned*>(&hh);
}
__device__ __forceinline__ float ex2(float x) {
    float r;
    asm("ex2.approx.f32 %0, %1;" : "=f"(r) : "f"(x));
    return r;
}
__device__ __forceinline__ void mma16816(
    float& c0, float& c1, float& c2, float& c3,
    unsigned a0, unsigned a1, unsigned a2, unsigned a3,
    unsigned b0, unsigned b1) {
    asm volatile(
        "mma.sync.aligned.m16n8k16.row.col.f32.f16.f16.f32 "
        "{%0,%1,%2,%3},{%4,%5,%6,%7},{%8,%9},{%0,%1,%2,%3};"
        : "+f"(c0), "+f"(c1), "+f"(c2), "+f"(c3)
        : "r"(a0), "r"(a1), "r"(a2), "r"(a3), "r"(b0), "r"(b1));
}
__device__ __forceinline__ void cp16(unsigned saddr, const void* g) {
    asm volatile("cp.async.cg.shared.global [%0], [%1], 16;"
                 :: "r"(saddr), "l"(g) : "memory");
}
#define LDSM4(r, a)                                                           \
    asm volatile("ldmatrix.sync.aligned.m8n8.x4.shared.b16 {%0,%1,%2,%3},[%4];" \
                 : "=r"((r)[0]), "=r"((r)[1]), "=r"((r)[2]), "=r"((r)[3])     \
                 : "r"(a))
#define LDSM4T(r, a)                                                          \
    asm volatile("ldmatrix.sync.aligned.m8n8.x4.trans.shared.b16 {%0,%1,%2,%3},[%4];" \
                 : "=r"((r)[0]), "=r"((r)[1]), "=r"((r)[2]), "=r"((r)[3])     \
                 : "r"(a))

// ---------------------------------------------------------------------------
// prepass: elementwise fp32 -> fp16 (single plane)
// ---------------------------------------------------------------------------
__global__ __launch_bounds__(256) void conv_half(
    const float4* __restrict__ src, uint4* __restrict__ dst, int nvec8)
{
    int i = blockIdx.x * 256 + threadIdx.x;
    if (i >= nvec8) return;
    float4 f0 = src[2 * i], f1 = src[2 * i + 1];
    uint4 h;
    h.x = pkh(f0.x, f0.y); h.y = pkh(f0.z, f0.w);
    h.z = pkh(f1.x, f1.y); h.w = pkh(f1.z, f1.w);
    dst[i] = h;
}
// prepass: transpose + fp16 round for BOTH weight matrices in one launch.
// z=0: w_qkv [K=1024][N=3072] -> wq [3072][1024], q-cols (n<1024) scaled by
//      0.125*log2(e) (folds q-scale AND exp2-domain conversion into W).
// z=1: w_out [1024][1024] -> wo.
__global__ void tr_half2(const float* __restrict__ s0, __half* __restrict__ d0,
                         const float* __restrict__ s1, __half* __restrict__ d1)
{
    __shared__ float tile[32][33];
    const int z = blockIdx.z;
    const int N = z ? DMODEL : QKVC;
    if (blockIdx.x * 32 >= (unsigned)N) return;
    const float* src = z ? s1 : s0;
    __half* dst = z ? d1 : d0;
    const int K = DMODEL;
    const int n0 = blockIdx.x * 32, k0 = blockIdx.y * 32;
    const int tx = threadIdx.x, ty = threadIdx.y;
    #pragma unroll
    for (int j = ty; j < 32; j += 8)
        tile[j][tx] = src[(size_t)(k0 + j) * N + n0 + tx];
    __syncthreads();
    #pragma unroll
    for (int j = ty; j < 32; j += 8) {
        float sc = (!z && n0 + j < DMODEL) ? 0.18033688f : 1.0f;  // 0.125*log2e
        dst[(size_t)(n0 + j) * K + k0 + tx] = __float2half_rn(tile[tx][j] * sc);
    }
}

// ---------------------------------------------------------------------------
// 1-term fp16 HMMA GEMM, 4-stage cp.async, single barrier per chunk,
// ldmatrix fragment loads. (FROZEN — best measured config.)
// A [M][K] fp16, B [N][K] fp16. Out: fp32 Cf OR fp16 Ch.
// 128x128 CTA tile, 256 thr (2x4 warps -> 64x32 warp tile), K chunk 32.
// ---------------------------------------------------------------------------
#define TILE_B 10240
#define STG_B  20480
#define NSTG   4
#define GSMEM  (NSTG * STG_B)

__device__ __forceinline__ void gload(
    unsigned sb, int st, int tid,
    const __half* a, const __half* b, int K, int k0)
{
    const __half* base[2] = {a, b};
    const int rlo = tid >> 2;
    const int pel = (tid & 3) << 3;
    const int pby = (tid & 3) << 4;
    #pragma unroll
    for (int i = 0; i < 4; i++) {
        const int tl  = i >> 1;
        const int row = ((i & 1) << 6) + rlo;
        cp16(sb + st * STG_B + tl * TILE_B + row * 80 + pby,
             base[tl] + (size_t)row * K + k0 + pel);
    }
    asm volatile("cp.async.commit_group;" ::: "memory");
}

__global__ __launch_bounds__(256, 2) void gemm_mma(
    const __half* __restrict__ A, const __half* __restrict__ B,
    float* __restrict__ Cf, __half* __restrict__ Ch, int M, int N, int K)
{
    extern __shared__ char dsm[];
    const unsigned sb = smem_u32(dsm);

    const int tid = threadIdx.x;
    const int wid = tid >> 5, lid = tid & 31;
    const int g = lid >> 2, t = lid & 3;
    const int wm = (wid >> 2) * 64;
    const int wn = (wid & 3) * 32;
    const int m0 = blockIdx.y * 128, n0 = blockIdx.x * 128;

    const __half* a_p = A + (size_t)m0 * K;
    const __half* b_p = B + (size_t)n0 * K;

    const unsigned aoff =
        (unsigned)((wm + (lid & 7) + ((lid >> 3) & 1) * 8) * 80 + (lid >> 4) * 16);
    const unsigned boff =
        (unsigned)(TILE_B + (wn + (lid & 7)) * 80 + (lid >> 3) * 16);

    float acc[4][4][4];
    #pragma unroll
    for (int i = 0; i < 4; i++)
        #pragma unroll
        for (int j = 0; j < 4; j++)
            #pragma unroll
            for (int e = 0; e < 4; e++) acc[i][j][e] = 0.f;

    const int nk = K >> 5;
    gload(sb, 0, tid, a_p, b_p, K, 0);
    gload(sb, 1, tid, a_p, b_p, K, 32);
    gload(sb, 2, tid, a_p, b_p, K, 64);

    for (int kc = 0; kc < nk; kc++) {
        const int rem = nk - 1 - kc;
        if (rem >= 2)      asm volatile("cp.async.wait_group 2;" ::: "memory");
        else if (rem == 1) asm volatile("cp.async.wait_group 1;" ::: "memory");
        else               asm volatile("cp.async.wait_group 0;" ::: "memory");
        __syncthreads();

        if (kc + 3 < nk)
            gload(sb, (kc + 3) & 3, tid, a_p, b_p, K, (kc + 3) << 5);

        const unsigned stb = sb + (kc & 3) * STG_B;

        unsigned bf[4][4];
        #pragma unroll
        for (int tn = 0; tn < 4; tn++)
            LDSM4(bf[tn], stb + boff + tn * (8 * 80));

        #pragma unroll
        for (int s = 0; s < 2; s++) {
            unsigned a[4][4];
            #pragma unroll
            for (int tm = 0; tm < 4; tm++)
                LDSM4(a[tm], stb + aoff + tm * (16 * 80) + s * 32);
            #pragma unroll
            for (int tn = 0; tn < 4; tn++) {
                const unsigned b0 = bf[tn][2 * s], b1 = bf[tn][2 * s + 1];
                #pragma unroll
                for (int tm = 0; tm < 4; tm++) {
                    float* c = acc[tm][tn];
                    mma16816(c[0], c[1], c[2], c[3],
                             a[tm][0], a[tm][1], a[tm][2], a[tm][3], b0, b1);
                }
            }
        }
    }

    #pragma unroll
    for (int tm = 0; tm < 4; tm++) {
        #pragma unroll
        for (int tn = 0; tn < 4; tn++) {
            float* c = acc[tm][tn];
            size_t r0 = (size_t)(m0 + wm + tm * 16 + g) * N + n0 + wn + tn * 8 + 2 * t;
            if (Cf) {
                *reinterpret_cast<float2*>(Cf + r0)                 = make_float2(c[0], c[1]);
                *reinterpret_cast<float2*>(Cf + r0 + 8 * (size_t)N) = make_float2(c[2], c[3]);
            } else {
                *reinterpret_cast<unsigned*>(Ch + r0) = pkh(c[0], c[1]);
                *reinterpret_cast<unsigned*>(Ch + r0 + 8 * (size_t)N) = pkh(c[2], c[3]);
            }
        }
    }
}

// ---------------------------------------------------------------------------
// fp16 HMMA sliding-window attention, log2-domain softmax (scores arrive
// pre-scaled by log2(e) via the weight fold; all exps are bare MUFU.EX2).
// grid = (32, 64), 256 thr, occupancy 2. Q/K/V single fp16 plane.
// ---------------------------------------------------------------------------
#define RB    144
#define QPL   18432
#define ASMEM (5 * QPL)

__global__ __launch_bounds__(256, 2) void swa_mma(
    const __half* __restrict__ qkvh, __half* __restrict__ oh)
{
    extern __shared__ char sm[];
    const unsigned sb = smem_u32(sm);
    const int blkq = blockIdx.x;
    const int bh = blockIdx.y, b = bh >> 4, hh = bh & 15;
    const int tid = threadIdx.x, w = tid >> 5, lid = tid & 31;
    const int g = lid >> 2, t = lid & 3;
    const int q0 = blkq * 128;
    const size_t tokb = (size_t)b * NSEQ;

    const unsigned sQ = sb;
    const unsigned sK = sb + QPL;
    const unsigned sV = sb + 3 * QPL;

    {
        int r = tid >> 1;
        const __half* src = qkvh + (tokb + q0 + r) * QKVC + hh * DH + (tid & 1) * 32;
        unsigned dst = sQ + r * RB + (tid & 1) * 64;
        #pragma unroll
        for (int s = 0; s < 4; s++) cp16(dst + s * 16, src + s * 8);
    }
    asm volatile("cp.async.commit_group;" ::: "memory");

    const int cstart = (q0 >= 256) ? 0 : (q0 >= 128 ? 1 : 2);

    auto ldkv = [&](int c, int st) {
        const int kb = q0 - 256 + c * 128;
        const int r = tid & 127;
        const int isv = tid >> 7;
        const size_t row = tokb + kb + r;
        const int off = (isv ? 2 * DMODEL : DMODEL) + hh * DH;
        const __half* sh = qkvh + row * QKVC + off;
        unsigned base = (isv ? sV : sK) + st * QPL + r * RB;
        #pragma unroll
        for (int s = 0; s < 8; s++) cp16(base + s * 16, sh + s * 8);
        asm volatile("cp.async.commit_group;" ::: "memory");
    };

    ldkv(cstart, 0);
    asm volatile("cp.async.wait_group 0;" ::: "memory");
    __syncthreads();

    unsigned qh[4][4];
    {
        unsigned ab = sQ + (w * 16 + (lid & 15)) * RB + (lid >> 4) * 16;
        #pragma unroll
        for (int ks = 0; ks < 4; ks++) LDSM4(qh[ks], ab + ks * 32);
    }

    float O[8][4];
    #pragma unroll
    for (int i = 0; i < 8; i++)
        #pragma unroll
        for (int e = 0; e < 4; e++) O[i][e] = 0.f;
    float m0 = -1e30f, m1 = -1e30f, l0 = 0.f, l1 = 0.f;
    const int qi0 = q0 + w * 16 + g, qi1 = qi0 + 8;

    const unsigned klane = (lid & 7) * RB + (lid >> 3) * 16;
    const unsigned vlane = (lid & 15) * RB + (lid >> 4) * 16;

    for (int c = cstart; c <= 2; ++c) {
        const int st = (c - cstart) & 1;
        if (c < 2) ldkv(c + 1, st ^ 1);

        const int kb = q0 - 256 + c * 128;
        const int tnlo = (c == 0) ? 2 * w : 0;
        const int tnhi = (c == 2) ? 2 * w + 1 : 15;
        const int jlo = (c == 0) ? w : 0;
        const int jhi = (c == 2) ? w : 7;
        const unsigned kbase = sK + st * QPL + klane;
        const unsigned vbase = sV + st * QPL + vlane;

        #pragma unroll
        for (int hf = 0; hf < 2; hf++) {
            const int lo  = (tnlo > hf * 8) ? tnlo : hf * 8;
            const int hi2 = (tnhi < hf * 8 + 7) ? tnhi : hf * 8 + 7;
            if (lo > hi2) continue;

            float S[8][4];
            #pragma unroll
            for (int i = 0; i < 8; i++) {
                const int tt = hf * 8 + i;
                if (tt < lo || tt > hi2) continue;
                S[i][0] = S[i][1] = S[i][2] = S[i][3] = 0.f;
                #pragma unroll
                for (int sp = 0; sp < 2; sp++) {
                    unsigned kh[4];
                    LDSM4(kh, kbase + tt * (8 * RB) + sp * 64);
                    float* c4 = S[i];
                    mma16816(c4[0], c4[1], c4[2], c4[3],
                             qh[2*sp][0], qh[2*sp][1], qh[2*sp][2], qh[2*sp][3], kh[0], kh[1]);
                    mma16816(c4[0], c4[1], c4[2], c4[3],
                             qh[2*sp+1][0], qh[2*sp+1][1], qh[2*sp+1][2], qh[2*sp+1][3], kh[2], kh[3]);
                }
            }

            float cm0 = -1e30f, cm1 = -1e30f;
            #pragma unroll
            for (int i = 0; i < 8; i++) {
                const int tt = hf * 8 + i;
                if (tt < lo || tt > hi2) continue;
                const int k0c = kb + tt * 8 + 2 * t;
                if (c == 0) {
                    if (k0c     < qi0 - 255) S[i][0] = -1e30f;
                    if (k0c + 1 < qi0 - 255) S[i][1] = -1e30f;
                    if (k0c     < qi1 - 255) S[i][2] = -1e30f;
                    if (k0c + 1 < qi1 - 255) S[i][3] = -1e30f;
                } else if (c == 2) {
                    if (k0c     > qi0) S[i][0] = -1e30f;
                    if (k0c + 1 > qi0) S[i][1] = -1e30f;
                    if (k0c     > qi1) S[i][2] = -1e30f;
                    if (k0c + 1 > qi1) S[i][3] = -1e30f;
                }
                cm0 = fmaxf(cm0, fmaxf(S[i][0], S[i][1]));
                cm1 = fmaxf(cm1, fmaxf(S[i][2], S[i][3]));
            }
            cm0 = fmaxf(cm0, __shfl_xor_sync(0xFFFFFFFFu, cm0, 1));
            cm0 = fmaxf(cm0, __shfl_xor_sync(0xFFFFFFFFu, cm0, 2));
            cm1 = fmaxf(cm1, __shfl_xor_sync(0xFFFFFFFFu, cm1, 1));
            cm1 = fmaxf(cm1, __shfl_xor_sync(0xFFFFFFFFu, cm1, 2));
            const float mn0 = fmaxf(m0, cm0), mn1 = fmaxf(m1, cm1);
            const float corr0 = ex2(m0 - mn0), corr1 = ex2(m1 - mn1);
            m0 = mn0; m1 = mn1;

            float ls0 = 0.f, ls1 = 0.f;
            #pragma unroll
            for (int i = 0; i < 8; i++) {
                const int tt = hf * 8 + i;
                if (tt < lo || tt > hi2) continue;
                S[i][0] = ex2(S[i][0] - m0);
                S[i][1] = ex2(S[i][1] - m0);
                S[i][2] = ex2(S[i][2] - m1);
                S[i][3] = ex2(S[i][3] - m1);
                ls0 += S[i][0] + S[i][1];
                ls1 += S[i][2] + S[i][3];
            }
            l0 = l0 * corr0 + ls0;
            l1 = l1 * corr1 + ls1;
            #pragma unroll
            for (int i = 0; i < 8; i++) {
                O[i][0] *= corr0; O[i][1] *= corr0;
                O[i][2] *= corr1; O[i][3] *= corr1;
            }

            #pragma unroll
            for (int j = 0; j < 4; j++) {
                const int jj2 = hf * 4 + j;
                if (jj2 < jlo || jj2 > jhi) continue;
                unsigned ph[4];
                ph[0] = pkh(S[2*j][0],   S[2*j][1]);
                ph[1] = pkh(S[2*j][2],   S[2*j][3]);
                ph[2] = pkh(S[2*j+1][0], S[2*j+1][1]);
                ph[3] = pkh(S[2*j+1][2], S[2*j+1][3]);
                #pragma unroll
                for (int tp = 0; tp < 4; tp++) {
                    unsigned vh[4];
                    LDSM4T(vh, vbase + jj2 * (16 * RB) + tp * 32);
                    float* cA = O[2 * tp];
                    float* cB = O[2 * tp + 1];
                    mma16816(cA[0], cA[1], cA[2], cA[3],
                             ph[0], ph[1], ph[2], ph[3], vh[0], vh[1]);
                    mma16816(cB[0], cB[1], cB[2], cB[3],
                             ph[0], ph[1], ph[2], ph[3], vh[2], vh[3]);
                }
            }
        }

        if (c < 2) asm volatile("cp.async.wait_group 0;" ::: "memory");
        __syncthreads();
    }

    l0 += __shfl_xor_sync(0xFFFFFFFFu, l0, 1);
    l0 += __shfl_xor_sync(0xFFFFFFFFu, l0, 2);
    l1 += __shfl_xor_sync(0xFFFFFFFFu, l1, 1);
    l1 += __shfl_xor_sync(0xFFFFFFFFu, l1, 2);
    const float i0 = 1.f / l0, i1 = 1.f / l1;
    const size_t t0 = (tokb + q0 + w * 16 + g) * DMODEL + hh * DH;
    const size_t t1 = t0 + 8 * DMODEL;
    #pragma unroll
    for (int tp = 0; tp < 8; tp++) {
        const int col = tp * 8 + 2 * t;
        *reinterpret_cast<unsigned*>(oh + t0 + col) = pkh(O[tp][0] * i0, O[tp][1] * i0);
        *reinterpret_cast<unsigned*>(oh + t1 + col) = pkh(O[tp][2] * i1, O[tp][3] * i1);
    }
}

// ---------------------------------------------------------------------------
extern "C" void kernel_launch(void* const* d_in, const int* in_sizes, int n_in,
                              void* d_out, int out_size)
{
    const float* x     = (const float*)d_in[0];
    const float* w_qkv = (const float*)d_in[1];
    const float* w_out = (const float*)d_in[2];
    float*       out   = (float*)d_out;

    __half *xh, *qkvh, *ah, *wq, *wo;
    cudaGetSymbolAddress((void**)&xh, g_xh);
    cudaGetSymbolAddress((void**)&qkvh, g_qkvh);
    cudaGetSymbolAddress((void**)&ah, g_ah);
    cudaGetSymbolAddress((void**)&wq, g_wq);
    cudaGetSymbolAddress((void**)&wo, g_wo);

    cudaFuncSetAttribute(gemm_mma, cudaFuncAttributeMaxDynamicSharedMemorySize, GSMEM);
    cudaFuncSetAttribute(swa_mma, cudaFuncAttributeMaxDynamicSharedMemorySize, ASMEM);

    const int nv8 = MTOK * DMODEL / 8;
    conv_half<<<(nv8 + 255) / 256, 256>>>((const float4*)x, (uint4*)xh, nv8);
    tr_half2<<<dim3(QKVC / 32, DMODEL / 32, 2), dim3(32, 8)>>>(w_qkv, wq, w_out, wo);

    gemm_mma<<<dim3(QKVC / 128, MTOK / 128), 256, GSMEM>>>(
        xh, wq, nullptr, qkvh, MTOK, QKVC, DMODEL);
    swa_mma<<<dim3(NSEQ / 128, BPAR * NH), 256, ASMEM>>>(qkvh, ah);
    gemm_mma<<<dim3(DMODEL / 128, MTOK / 128), 256, GSMEM>>>(
        ah, wo, out, nullptr, MTOK, DMODEL, DMODEL);
}